// round 9
// baseline (speedup 1.0000x reference)
#include <cuda_runtime.h>
#include <cuda_bf16.h>
#include <cstdint>

// Problem constants
#define B_SZ  4
#define SEQ   4096
#define HIDN  1024
#define NH    16
#define HD    64
#define MTOT  (B_SZ * SEQ)   // 16384 tokens
#define MK    ((size_t)MTOT * HIDN)

// Arch-feature gate: tcgen05/TMEM only legal in arch-specific ('a') passes.
#if defined(__CUDA_ARCH__) && (defined(__CUDA_ARCH_FEAT_SM103_ALL) || defined(__CUDA_ARCH_FEAT_SM100_ALL) || defined(__CUDA_ARCH_FEAT_SM101_ALL))
#define HAS_TC 1
#else
#define HAS_TC 0
#endif

// Scratch (device globals: no allocations allowed in kernel_launch)
static __device__ float g_q[MK];
static __device__ float g_k[MK];
static __device__ float g_v[MK];
static __device__ float g_x[MK];                       // fp32 x (fallback path)
static __device__ __nv_bfloat16 g_ah[3 * MK];          // split activations hi (q,k,v inputs)
static __device__ __nv_bfloat16 g_al[3 * MK];          // split activations lo
static __device__ __nv_bfloat16 g_xh[MK];              // attention output hi (permuted)
static __device__ __nv_bfloat16 g_xl[MK];              // attention output lo
static __device__ __nv_bfloat16 g_wbh[4 * MK / MTOT * HIDN]; // weights^T hi [4][N][K]
static __device__ __nv_bfloat16 g_wbl[4 * MK / MTOT * HIDN]; // weights^T lo

// ===========================================================================
// GEMM tile geometry: 128x256 tile, BK=64, SS-mode, everything pre-split bf16
// ===========================================================================
#define GBM 128
#define GBN 256
#define GBK 64
#define GKD 1024
#define GNCH (GKD / GBK)          // 16 stages

#define SM_TMEM   0
#define SM_MBAR   8               // 2 mbarriers at 8,16
#define SM_BUF    1024
#define BUF_STRIDE 98304          // 96 KB/stage: AH 16K | AL 16K | BH 32K | BL 32K
#define OFF_AH 0
#define OFF_AL 16384
#define OFF_BH 32768
#define OFF_BL 65536
#define GEMM_SMEM_BYTES (1024 + 2 * BUF_STRIDE)   // 197632

// idesc: dtype=F32(1)<<4 | atype=BF16(1)<<7 | btype=BF16(1)<<10 | (N/8)<<17 | (M/16)<<24
#define IDESC_BF16 ((1u << 4) | (1u << 7) | (1u << 10) | ((GBN / 8) << 17) | ((GBM / 16) << 24))

extern __shared__ char dynsmem[];

#if HAS_TC
// ---------------------------------------------------------------------------
// tcgen05 helpers (arch-specific pass only)
// ---------------------------------------------------------------------------
__device__ __forceinline__ uint32_t s2u(const void* p) {
    uint32_t a;
    asm("{ .reg .u64 t; cvta.to.shared.u64 t, %1; cvt.u32.u64 %0, t; }"
        : "=r"(a) : "l"(p));
    return a;
}
__device__ __forceinline__ uint64_t to_global(const void* p) {
    uint64_t g;
    asm("cvta.to.global.u64 %0, %1;" : "=l"(g) : "l"(p));
    return g;
}
__device__ __forceinline__ bool elect1() {
    uint32_t p;
    asm volatile("{ .reg .pred p; elect.sync _|p, 0xFFFFFFFF; selp.b32 %0, 1, 0, p; }"
                 : "=r"(p));
    return p != 0;
}
__device__ __forceinline__ void mbar_init(uint32_t mbar, uint32_t cnt) {
    asm volatile("mbarrier.init.shared.b64 [%0], %1;" :: "r"(mbar), "r"(cnt) : "memory");
}
__device__ __forceinline__ void mbar_wait(uint32_t mbar, uint32_t parity) {
    asm volatile(
        "{\n\t"
        ".reg .pred P;\n\t"
        "WL%=:\n\t"
        "mbarrier.try_wait.parity.acquire.cta.shared::cta.b64 P, [%0], %1, 0x989680;\n\t"
        "@P bra.uni WD%=;\n\t"
        "bra.uni WL%=;\n\t"
        "WD%=:\n\t"
        "}"
        :: "r"(mbar), "r"(parity) : "memory");
}
__device__ __forceinline__ void tmem_alloc(uint32_t smem_dst, uint32_t ncols) {
    asm volatile("tcgen05.alloc.cta_group::1.sync.aligned.shared::cta.b32 [%0], %1;"
                 :: "r"(smem_dst), "r"(ncols) : "memory");
}
__device__ __forceinline__ void tmem_relinquish() {
    asm volatile("tcgen05.relinquish_alloc_permit.cta_group::1.sync.aligned;");
}
__device__ __forceinline__ void tmem_dealloc(uint32_t tmem, uint32_t ncols) {
    asm volatile("tcgen05.dealloc.cta_group::1.sync.aligned.b32 %0, %1;"
                 :: "r"(tmem), "r"(ncols));
}
__device__ __forceinline__ void tc_commit(uint32_t mbar) {
    asm volatile("tcgen05.commit.cta_group::1.mbarrier::arrive::one.shared::cluster.b64 [%0];"
                 :: "r"(mbar) : "memory");
}
__device__ __forceinline__ void tc_fence_after() {
    asm volatile("tcgen05.fence::after_thread_sync;" ::: "memory");
}
__device__ __forceinline__ void fence_async_smem() {
    asm volatile("fence.proxy.async.shared::cta;" ::: "memory");
}
__device__ __forceinline__ void tc_wait_ld() {
    asm volatile("tcgen05.wait::ld.sync.aligned;" ::: "memory");
}
__device__ __forceinline__ void cp16(uint32_t dst_smem, uint64_t src_gmem) {
    asm volatile("cp.async.cg.shared.global [%0], [%1], 16;"
                 :: "r"(dst_smem), "l"(src_gmem) : "memory");
}
__device__ __forceinline__ void cp_commit() {
    asm volatile("cp.async.commit_group;" ::: "memory");
}
__device__ __forceinline__ void cp_wait1() {
    asm volatile("cp.async.wait_group 1;" ::: "memory");
}
__device__ __forceinline__ void cp_wait0() {
    asm volatile("cp.async.wait_group 0;" ::: "memory");
}

// SS bf16 MMA, cta_group::1
__device__ __forceinline__ void mma_bf16(uint32_t d_tmem, uint64_t a_desc,
                                         uint64_t b_desc, uint32_t idesc, uint32_t en) {
    asm volatile(
        "{\n\t"
        ".reg .pred p;\n\t"
        "setp.ne.u32 p, %4, 0;\n\t"
        "tcgen05.mma.cta_group::1.kind::f16 [%0], %1, %2, %3, {%5, %5, %5, %5}, p;\n\t"
        "}"
        :: "r"(d_tmem), "l"(a_desc), "l"(b_desc), "r"(idesc), "r"(en), "r"(0u)
        : "memory");
}

#define TC_LD_X32(r, addr)                                                     \
    asm volatile(                                                              \
        "tcgen05.ld.sync.aligned.32x32b.x32.b32 "                              \
        "{%0, %1, %2, %3, %4, %5, %6, %7, "                                    \
        " %8, %9, %10, %11, %12, %13, %14, %15, "                              \
        " %16, %17, %18, %19, %20, %21, %22, %23, "                            \
        " %24, %25, %26, %27, %28, %29, %30, %31}, [%32];"                     \
        : "=r"((r)[0]),  "=r"((r)[1]),  "=r"((r)[2]),  "=r"((r)[3]),           \
          "=r"((r)[4]),  "=r"((r)[5]),  "=r"((r)[6]),  "=r"((r)[7]),           \
          "=r"((r)[8]),  "=r"((r)[9]),  "=r"((r)[10]), "=r"((r)[11]),          \
          "=r"((r)[12]), "=r"((r)[13]), "=r"((r)[14]), "=r"((r)[15]),          \
          "=r"((r)[16]), "=r"((r)[17]), "=r"((r)[18]), "=r"((r)[19]),          \
          "=r"((r)[20]), "=r"((r)[21]), "=r"((r)[22]), "=r"((r)[23]),          \
          "=r"((r)[24]), "=r"((r)[25]), "=r"((r)[26]), "=r"((r)[27]),          \
          "=r"((r)[28]), "=r"((r)[29]), "=r"((r)[30]), "=r"((r)[31])           \
        : "r"(addr))

#define SWZ(o) ((o) ^ (((o) >> 3) & 0x70))

// SW128 descriptor: layout=2<<61 | version=1<<46 | SBO=64<<32 | LBO=1<<16
__device__ __forceinline__ uint64_t mkdesc(uint32_t smem_addr) {
    return 0x4000404000010000ull | ((uint64_t)(smem_addr >> 4) & 0x3FFF);
}

// Issue all cp.async for stage kt into slot kt&1 (A hi/lo + B hi/lo; 24/thread).
__device__ __forceinline__ void issue_cp(uint32_t sb, uint64_t ahg, uint64_t alg,
                                         uint64_t whg, uint64_t wlg,
                                         int row0, int col0, int kt, int tid) {
    const uint32_t bufu = sb + SM_BUF + (kt & 1) * BUF_STRIDE;
    const int kbase = kt * GBK;
#pragma unroll
    for (int j = 0; j < 4; j++) {                 // A: 128 rows x 8 granules/plane
        const int c = tid + 256 * j;
        const int r = c >> 3, k8 = c & 7;
        const uint64_t so = ((uint64_t)(row0 + r) * GKD + kbase + k8 * 8) * 2;
        const uint32_t doff = SWZ((uint32_t)(r * 128 + k8 * 16));
        cp16(bufu + OFF_AH + doff, ahg + so);
        cp16(bufu + OFF_AL + doff, alg + so);
    }
#pragma unroll
    for (int j = 0; j < 8; j++) {                 // B: 256 rows x 8 granules/plane
        const int c = tid + 256 * j;
        const int n = c >> 3, k8 = c & 7;
        const uint64_t so = ((uint64_t)(col0 + n) * GKD + kbase + k8 * 8) * 2;
        const uint32_t doff = SWZ((uint32_t)(n * 128 + k8 * 16));
        cp16(bufu + OFF_BH + doff, whg + so);
        cp16(bufu + OFF_BL + doff, wlg + so);
    }
    cp_commit();
}

// ---------------------------------------------------------------------------
// GEMM core: C[128,256 tile] = (Ah+Al) @ (Wh+Wl)^T (3-term split) + bias
// All operands pre-split bf16 [rows, K] row-major in global.
// ---------------------------------------------------------------------------
__device__ __forceinline__ void gemm_core(const __nv_bfloat16* __restrict__ Ah,
                                          const __nv_bfloat16* __restrict__ Al,
                                          const __nv_bfloat16* __restrict__ Wh,
                                          const __nv_bfloat16* __restrict__ Wl,
                                          const float* __restrict__ bias,
                                          float* __restrict__ C)
{
    const uint32_t sb = s2u(dynsmem);
    const int tid  = threadIdx.x;
    const int row0 = blockIdx.y * GBM;
    const int col0 = blockIdx.x * GBN;

    if (tid < 32) {
        tmem_alloc(sb + SM_TMEM, 256);
        tmem_relinquish();
    }
    if (tid == 0) {
        mbar_init(sb + SM_MBAR + 0, 1);
        mbar_init(sb + SM_MBAR + 8, 1);
    }
    __syncthreads();

    uint32_t tmem;
    asm volatile("ld.shared.b32 %0, [%1];" : "=r"(tmem) : "r"(sb + SM_TMEM));

    const uint64_t ahg = to_global(Ah);
    const uint64_t alg = to_global(Al);
    const uint64_t whg = to_global(Wh);
    const uint64_t wlg = to_global(Wl);

    // Prologue: both stage slots in flight.
    issue_cp(sb, ahg, alg, whg, wlg, row0, col0, 0, tid);
    issue_cp(sb, ahg, alg, whg, wlg, row0, col0, 1, tid);

#pragma unroll 1
    for (int kt = 0; kt < GNCH; kt++) {
        // Stage kt data must be resident (allow the newer group in flight).
        if (kt == GNCH - 1) cp_wait0(); else cp_wait1();
        fence_async_smem();
        __syncthreads();

        // 12 MMAs: (hh, hl, lh) x 4 k-steps.
        if (tid < 32) {
            if (elect1()) {
                const uint32_t bufu = sb + SM_BUF + (kt & 1) * BUF_STRIDE;
                const uint64_t dAh = mkdesc(bufu + OFF_AH);
                const uint64_t dAl = mkdesc(bufu + OFF_AL);
                const uint64_t dBh = mkdesc(bufu + OFF_BH);
                const uint64_t dBl = mkdesc(bufu + OFF_BL);
#pragma unroll
                for (int ks = 0; ks < 4; ks++)
                    mma_bf16(tmem, dAh + 2 * ks, dBh + 2 * ks, IDESC_BF16,
                             (kt == 0 && ks == 0) ? 0u : 1u);
#pragma unroll
                for (int ks = 0; ks < 4; ks++)
                    mma_bf16(tmem, dAh + 2 * ks, dBl + 2 * ks, IDESC_BF16, 1u);
#pragma unroll
                for (int ks = 0; ks < 4; ks++)
                    mma_bf16(tmem, dAl + 2 * ks, dBh + 2 * ks, IDESC_BF16, 1u);
                tc_commit(sb + SM_MBAR + (kt & 1) * 8);
            }
        }

        // Refill this slot for stage kt+2 once MMA(kt) has drained it.
        if (kt + 2 < GNCH) {
            mbar_wait(sb + SM_MBAR + (kt & 1) * 8, (uint32_t)((kt >> 1) & 1));
            issue_cp(sb, ahg, alg, whg, wlg, row0, col0, kt + 2, tid);
        }
    }

    // Drain the final MMA batch (in-order completion covers all prior).
    {
        const int kt = GNCH - 1;
        mbar_wait(sb + SM_MBAR + (kt & 1) * 8, (uint32_t)((kt >> 1) & 1));
    }
    tc_fence_after();

    // Epilogue: warps 0-3 read D from TMEM, add bias, store.
    if (tid < 128) {
        const int m = row0 + tid;
        float* Crow = C + (size_t)m * HIDN + col0;
#pragma unroll
        for (int n0 = 0; n0 < GBN; n0 += 32) {
            uint32_t r[32];
            TC_LD_X32(r, tmem + n0);
            tc_wait_ld();
#pragma unroll
            for (int j = 0; j < 32; j += 4) {
                float4 o;
                o.x = __uint_as_float(r[j + 0]) + bias[col0 + n0 + j + 0];
                o.y = __uint_as_float(r[j + 1]) + bias[col0 + n0 + j + 1];
                o.z = __uint_as_float(r[j + 2]) + bias[col0 + n0 + j + 2];
                o.w = __uint_as_float(r[j + 3]) + bias[col0 + n0 + j + 3];
                *(float4*)(Crow + n0 + j) = o;
            }
        }
    }
    __syncthreads();
    if (tid < 32) tmem_dealloc(tmem, 256);
}
#endif  // HAS_TC

// Merged QKV GEMM (z selects pre-split input/weight/bias/output).
__global__ __launch_bounds__(256, 1)
void gemm_qkv(const __nv_bfloat16* __restrict__ ah, const __nv_bfloat16* __restrict__ al,
              const __nv_bfloat16* __restrict__ wh, const __nv_bfloat16* __restrict__ wl,
              const float* __restrict__ bq, const float* __restrict__ bk,
              const float* __restrict__ bv,
              float* __restrict__ oq, float* __restrict__ ok, float* __restrict__ ov)
{
#if HAS_TC
    const int z = blockIdx.z;
    const float* bias = (z == 0) ? bq : (z == 1) ? bk : bv;
    float* C = (z == 0) ? oq : (z == 1) ? ok : ov;
    const size_t ao = (size_t)z * MK;
    const size_t wo = (size_t)z * HIDN * HIDN;
    gemm_core(ah + ao, al + ao, wh + wo, wl + wo, bias, C);
#endif
}

// Single GEMM (output projection; also the runtime capability probe).
__global__ __launch_bounds__(256, 1)
void gemm_single(const __nv_bfloat16* __restrict__ ah, const __nv_bfloat16* __restrict__ al,
                 const __nv_bfloat16* __restrict__ wh, const __nv_bfloat16* __restrict__ wl,
                 const float* __restrict__ bias, float* __restrict__ C)
{
#if HAS_TC
    gemm_core(ah, al, wh, wl, bias, C);
#endif
}

// ===========================================================================
// Activation split: fp32 q/k/v -> bf16 hi/lo (z selects source matrix).
// ===========================================================================
__global__ __launch_bounds__(256)
void split_acts(const float* __restrict__ q, const float* __restrict__ k,
                const float* __restrict__ v,
                __nv_bfloat16* __restrict__ ah, __nv_bfloat16* __restrict__ al)
{
    const int z = blockIdx.z;
    const float* src = (z == 0) ? q : (z == 1) ? k : v;
    __nv_bfloat16* dh = ah + (size_t)z * MK;
    __nv_bfloat16* dl = al + (size_t)z * MK;
    const size_t i = ((size_t)blockIdx.x * 256 + threadIdx.x) * 4;
    const float4 x = *(const float4*)(src + i);
    __nv_bfloat162 h0 = __floats2bfloat162_rn(x.x, x.y);
    __nv_bfloat162 h1 = __floats2bfloat162_rn(x.z, x.w);
    const float2 f0 = __bfloat1622float2(h0);
    const float2 f1 = __bfloat1622float2(h1);
    __nv_bfloat162 l0 = __floats2bfloat162_rn(x.x - f0.x, x.y - f0.y);
    __nv_bfloat162 l1 = __floats2bfloat162_rn(x.z - f1.x, x.w - f1.y);
    *(uint2*)(dh + i) = make_uint2(*(uint32_t*)&h0, *(uint32_t*)&h1);
    *(uint2*)(dl + i) = make_uint2(*(uint32_t*)&l0, *(uint32_t*)&l1);
}

// ===========================================================================
// Weight prep: WTh[n][k] = bf16(W[k][n]), WTl = bf16(residual). 4 matrices.
// ===========================================================================
__global__ __launch_bounds__(256)
void prep_weights(const float* __restrict__ s0, const float* __restrict__ s1,
                  const float* __restrict__ s2, const float* __restrict__ s3,
                  __nv_bfloat16* __restrict__ dh, __nv_bfloat16* __restrict__ dl)
{
    __shared__ float t[32][33];
    const float* src = (blockIdx.z == 0) ? s0 : (blockIdx.z == 1) ? s1
                     : (blockIdx.z == 2) ? s2 : s3;
    const size_t zo = (size_t)blockIdx.z * HIDN * HIDN;
    const int x0 = blockIdx.x * 32, y0 = blockIdx.y * 32;   // x: n, y: k
    const int tx = threadIdx.x & 31, ty0 = threadIdx.x >> 5;
#pragma unroll
    for (int i = 0; i < 4; i++) {
        const int ty = ty0 + i * 8;
        t[ty][tx] = src[(size_t)(y0 + ty) * HIDN + x0 + tx];
    }
    __syncthreads();
#pragma unroll
    for (int i = 0; i < 4; i++) {
        const int ty = ty0 + i * 8;
        const float val = t[tx][ty];
        const __nv_bfloat16 h = __float2bfloat16_rn(val);
        const __nv_bfloat16 l = __float2bfloat16_rn(val - __bfloat162float(h));
        const size_t di = zo + (size_t)(x0 + ty) * HIDN + (y0 + tx);
        dh[di] = h;
        dl[di] = l;
    }
}

// ===========================================================================
// Fallback SGEMM (fp32, proven path) — compiles on every arch.
// ===========================================================================
#define BM 128
#define BN 128
#define BK 16

__global__ __launch_bounds__(256, 2)
void sgemm_bias(const float* __restrict__ A, const float* __restrict__ W,
                const float* __restrict__ bias, float* __restrict__ C,
                int M, int N, int K)
{
    __shared__ float As[2][BK][BM];
    __shared__ float Bs[2][BK][BN];

    const int tid = threadIdx.x;
    const int tx  = tid & 15;
    const int ty  = tid >> 4;
    const int row0 = blockIdx.y * BM;
    const int col0 = blockIdx.x * BN;

    const int a_r = tid >> 2;
    const int a_k = (tid & 3) << 2;
    const int b_r = tid >> 5;
    const int b_c = (tid & 31) << 2;

    const float* Ab = A + (size_t)row0 * K;

    float acc[8][8];
#pragma unroll
    for (int i = 0; i < 8; i++)
#pragma unroll
        for (int j = 0; j < 8; j++) acc[i][j] = 0.f;

    {
        float4 a0 = *(const float4*)(Ab + (size_t)a_r * K + a_k);
        float4 a1 = *(const float4*)(Ab + (size_t)(a_r + 64) * K + a_k);
        float4 w0 = *(const float4*)(W + (size_t)b_r * N + col0 + b_c);
        float4 w1 = *(const float4*)(W + (size_t)(b_r + 8) * N + col0 + b_c);
        As[0][a_k + 0][a_r] = a0.x; As[0][a_k + 1][a_r] = a0.y;
        As[0][a_k + 2][a_r] = a0.z; As[0][a_k + 3][a_r] = a0.w;
        As[0][a_k + 0][a_r + 64] = a1.x; As[0][a_k + 1][a_r + 64] = a1.y;
        As[0][a_k + 2][a_r + 64] = a1.z; As[0][a_k + 3][a_r + 64] = a1.w;
        *(float4*)&Bs[0][b_r][b_c]     = w0;
        *(float4*)&Bs[0][b_r + 8][b_c] = w1;
    }
    __syncthreads();

    const int NT = K / BK;
    for (int kt = 0; kt < NT; kt++) {
        const int cur = kt & 1;

        float4 a0, a1, w0, w1;
        const bool more = (kt + 1 < NT);
        if (more) {
            const float* Ap = Ab + (size_t)(kt + 1) * BK;
            a0 = *(const float4*)(Ap + (size_t)a_r * K + a_k);
            a1 = *(const float4*)(Ap + (size_t)(a_r + 64) * K + a_k);
            const float* Wp = W + (size_t)(kt + 1) * BK * N + col0;
            w0 = *(const float4*)(Wp + (size_t)b_r * N + b_c);
            w1 = *(const float4*)(Wp + (size_t)(b_r + 8) * N + b_c);
        }

#pragma unroll
        for (int kk = 0; kk < BK; kk++) {
            float ar[8], br[8];
            *(float4*)(ar)     = *(const float4*)&As[cur][kk][ty * 8];
            *(float4*)(ar + 4) = *(const float4*)&As[cur][kk][ty * 8 + 4];
            *(float4*)(br)     = *(const float4*)&Bs[cur][kk][tx * 8];
            *(float4*)(br + 4) = *(const float4*)&Bs[cur][kk][tx * 8 + 4];
#pragma unroll
            for (int i = 0; i < 8; i++)
#pragma unroll
                for (int j = 0; j < 8; j++)
                    acc[i][j] += ar[i] * br[j];
        }

        if (more) {
            const int nxt = cur ^ 1;
            As[nxt][a_k + 0][a_r] = a0.x; As[nxt][a_k + 1][a_r] = a0.y;
            As[nxt][a_k + 2][a_r] = a0.z; As[nxt][a_k + 3][a_r] = a0.w;
            As[nxt][a_k + 0][a_r + 64] = a1.x; As[nxt][a_k + 1][a_r + 64] = a1.y;
            As[nxt][a_k + 2][a_r + 64] = a1.z; As[nxt][a_k + 3][a_r + 64] = a1.w;
            *(float4*)&Bs[nxt][b_r][b_c]     = w0;
            *(float4*)&Bs[nxt][b_r + 8][b_c] = w1;
        }
        __syncthreads();
    }

#pragma unroll
    for (int i = 0; i < 8; i++) {
        const size_t r = (size_t)(row0 + ty * 8 + i);
#pragma unroll
        for (int j4 = 0; j4 < 8; j4 += 4) {
            const int c = col0 + tx * 8 + j4;
            float4 o;
            o.x = acc[i][j4 + 0] + bias[c + 0];
            o.y = acc[i][j4 + 1] + bias[c + 1];
            o.z = acc[i][j4 + 2] + bias[c + 2];
            o.w = acc[i][j4 + 3] + bias[c + 3];
            *(float4*)&C[r * N + c] = o;
        }
    }
}

// ===========================================================================
// Per-token attention over the HEADS axis. float4-vectorized LDS; output
// written either fp32 (fallback) or pre-split bf16 hi/lo (tensor path).
// ===========================================================================
#define PD 68

__global__ __launch_bounds__(256)
void attn_kernel(const float* __restrict__ q, const float* __restrict__ k,
                 const float* __restrict__ v, const float* __restrict__ sw,
                 float* __restrict__ xf,
                 __nv_bfloat16* __restrict__ xh, __nv_bfloat16* __restrict__ xl,
                 float* __restrict__ attn_out, int write_attn, int out_bf16)
{
    __shared__ float sq[NH][PD], sk[NH][PD], sv[NH][PD];
    __shared__ float s_qk[NH][NH];
    __shared__ float s_qn2[NH], s_kn2[NH];
    __shared__ float s_at[NH][NH + 1];

    const int t   = blockIdx.x;
    const int b   = t >> 12;
    const int s   = t & 4095;
    const int tid = threadIdx.x;
    const size_t base = (size_t)t * HIDN;

    {
        const int row = tid >> 4;
        const int col = (tid & 15) << 2;
        *(float4*)&sq[row][col] = *(const float4*)(q + base + row * HD + col);
        *(float4*)&sk[row][col] = *(const float4*)(k + base + row * HD + col);
        *(float4*)&sv[row][col] = *(const float4*)(v + base + row * HD + col);
    }
    __syncthreads();

    if (tid < 32) {
        const int i = tid & 15;
        const float* p = (tid < 16) ? sq[i] : sk[i];
        float ss = 0.f;
#pragma unroll
        for (int d4 = 0; d4 < 16; d4++) {
            const float4 a = *(const float4*)(p + d4 * 4);
            ss += a.x * a.x + a.y * a.y + a.z * a.z + a.w * a.w;
        }
        if (tid < 16) s_qn2[i] = ss; else s_kn2[i] = ss;
    }
    {
        const int i = tid >> 4, j = tid & 15;
        float dot = 0.f;
#pragma unroll
        for (int d4 = 0; d4 < 16; d4++) {
            const float4 a = *(const float4*)&sq[i][d4 * 4];
            const float4 c = *(const float4*)&sk[j][d4 * 4];
            dot += a.x * c.x + a.y * c.y + a.z * c.z + a.w * c.w;
        }
        s_qk[i][j] = dot;
    }
    __syncthreads();

    if (tid < NH) {
        float w0, w1, w2;
        {
            const float x0 = sw[0], x1 = sw[1], x2 = sw[2];
            const float m  = fmaxf(x0, fmaxf(x1, x2));
            const float e0 = expf(x0 - m), e1 = expf(x1 - m), e2 = expf(x2 - m);
            const float inv = 1.f / (e0 + e1 + e2);
            w0 = e0 * inv; w1 = e1 * inv; w2 = e2 * inv;
        }
        const int i = tid;
        const float qn2 = s_qn2[i];
        const float qn  = sqrtf(qn2);
        float sc[NH];
        float mx = -1e30f;
#pragma unroll
        for (int j = 0; j < NH; j++) {
            const float qkv  = s_qk[i][j];
            const float kn2  = s_kn2[j];
            const float dotv = qkv * 0.125f;
            const float cosv = qkv / fmaxf(qn * sqrtf(kn2), 1e-8f);
            const float d2   = fmaxf(qn2 + kn2 - 2.f * qkv, 0.f);
            const float dstv = -sqrtf(d2);
            const float scv  = w0 * dotv + w1 * cosv + w2 * dstv;
            sc[j] = scv;
            mx = fmaxf(mx, scv);
        }
        float ssum = 0.f;
#pragma unroll
        for (int j = 0; j < NH; j++) { const float e = expf(sc[j] - mx); sc[j] = e; ssum += e; }
        const float inv = 1.f / ssum;
#pragma unroll
        for (int j = 0; j < NH; j++) {
            const float a = sc[j] * inv;
            s_at[i][j] = a;
            if (write_attn)
                attn_out[(size_t)t * (NH * NH) + i * NH + j] = a;
        }
    }
    __syncthreads();

    {
        const int i  = tid >> 4;
        const int db = (tid & 15) << 2;
        float4 o = make_float4(0.f, 0.f, 0.f, 0.f);
#pragma unroll
        for (int j = 0; j < NH; j++) {
            const float a = s_at[i][j];
            const float4 vv = *(const float4*)&sv[j][db];
            o.x += a * vv.x; o.y += a * vv.y; o.z += a * vv.z; o.w += a * vv.w;
        }
        // transpose(1,2).reshape fold: row = h*256 + s/16, col = (s%16)*64 + d
        const size_t dst = (size_t)b * ((size_t)SEQ * HIDN)
                         + (size_t)((i << 8) + (s >> 4)) * HIDN
                         + (size_t)((s & 15) << 6) + db;
        if (out_bf16) {
            __nv_bfloat162 h0 = __floats2bfloat162_rn(o.x, o.y);
            __nv_bfloat162 h1 = __floats2bfloat162_rn(o.z, o.w);
            const float2 f0 = __bfloat1622float2(h0);
            const float2 f1 = __bfloat1622float2(h1);
            __nv_bfloat162 l0 = __floats2bfloat162_rn(o.x - f0.x, o.y - f0.y);
            __nv_bfloat162 l1 = __floats2bfloat162_rn(o.z - f1.x, o.w - f1.y);
            *(uint2*)(xh + dst) = make_uint2(*(uint32_t*)&h0, *(uint32_t*)&h1);
            *(uint2*)(xl + dst) = make_uint2(*(uint32_t*)&l0, *(uint32_t*)&l1);
        } else {
            *(float4*)&xf[dst] = o;
        }
    }
}

// ===========================================================================
extern "C" void kernel_launch(void* const* d_in, const int* in_sizes, int n_in,
                              void* d_out, int out_size)
{
    const float* query = (const float*)d_in[0];
    const float* key_  = (const float*)d_in[1];
    const float* value = (const float*)d_in[2];
    const float* Wq    = (const float*)d_in[3];
    const float* bq    = (const float*)d_in[4];
    const float* Wk    = (const float*)d_in[5];
    const float* bk    = (const float*)d_in[6];
    const float* Wv    = (const float*)d_in[7];
    const float* bv    = (const float*)d_in[8];
    const float* Wo    = (const float*)d_in[9];
    const float* bo    = (const float*)d_in[10];
    const float* sw    = (const float*)d_in[11];
    float* out = (float*)d_out;

    float *gq, *gk, *gv, *gx;
    __nv_bfloat16 *gah, *gal, *gxh, *gxl, *gwh, *gwl;
    cudaGetSymbolAddress((void**)&gq,  g_q);
    cudaGetSymbolAddress((void**)&gk,  g_k);
    cudaGetSymbolAddress((void**)&gv,  g_v);
    cudaGetSymbolAddress((void**)&gx,  g_x);
    cudaGetSymbolAddress((void**)&gah, g_ah);
    cudaGetSymbolAddress((void**)&gal, g_al);
    cudaGetSymbolAddress((void**)&gxh, g_xh);
    cudaGetSymbolAddress((void**)&gxl, g_xl);
    cudaGetSymbolAddress((void**)&gwh, g_wbh);
    cudaGetSymbolAddress((void**)&gwl, g_wbl);

    const long long main_elems = (long long)MTOT * HIDN;
    const long long attn_elems = (long long)MTOT * NH * NH;
    const int write_attn = ((long long)out_size >= main_elems + attn_elems) ? 1 : 0;
    float* attn_ptr = out + main_elems;

    // Capability probe: stubbed (non-'a' pass) kernel uses only a few regs.
    cudaFuncAttributes fa;
    fa.numRegs = 0;
    cudaError_t perr = cudaFuncGetAttributes(&fa, gemm_single);
    const bool use_tc = (perr == cudaSuccess) && (fa.numRegs >= 24);

    if (use_tc) {
        cudaFuncSetAttribute(gemm_qkv, cudaFuncAttributeMaxDynamicSharedMemorySize,
                             GEMM_SMEM_BYTES);
        cudaFuncSetAttribute(gemm_single, cudaFuncAttributeMaxDynamicSharedMemorySize,
                             GEMM_SMEM_BYTES);

        // Prep: transpose+split weights; split activations.
        prep_weights<<<dim3(32, 32, 4), 256>>>(Wq, Wk, Wv, Wo, gwh, gwl);
        split_acts<<<dim3(MTOT * HIDN / 1024, 1, 3), 256>>>(query, key_, value, gah, gal);

        const size_t WSZ = (size_t)HIDN * HIDN;
        dim3 gq3(HIDN / GBN, MTOT / GBM, 3);   // (4, 128, 3)
        dim3 gg1(HIDN / GBN, MTOT / GBM);

        gemm_qkv<<<gq3, 256, GEMM_SMEM_BYTES>>>(gah, gal, gwh, gwl,
                                                bq, bk, bv, gq, gk, gv);

        attn_kernel<<<MTOT, 256>>>(gq, gk, gv, sw, gx, gxh, gxl,
                                   attn_ptr, write_attn, 1);

        gemm_single<<<gg1, 256, GEMM_SMEM_BYTES>>>(gxh, gxl, gwh + 3 * WSZ,
                                                   gwl + 3 * WSZ, bo, out);
    } else {
        // Fallback: proven fp32 path.
        dim3 gg(HIDN / BN, MTOT / BM);
        sgemm_bias<<<gg, 256>>>(query, Wq, bq, gq, MTOT, HIDN, HIDN);
        sgemm_bias<<<gg, 256>>>(key_,  Wk, bk, gk, MTOT, HIDN, HIDN);
        sgemm_bias<<<gg, 256>>>(value, Wv, bv, gv, MTOT, HIDN, HIDN);

        attn_kernel<<<MTOT, 256>>>(gq, gk, gv, sw, gx, nullptr, nullptr,
                                   attn_ptr, write_attn, 0);

        sgemm_bias<<<gg, 256>>>(gx, Wo, bo, out, MTOT, HIDN, HIDN);
    }
}

// round 12
// speedup vs baseline: 1.0076x; 1.0076x over previous
#include <cuda_runtime.h>
#include <cuda_bf16.h>
#include <cstdint>

// Problem constants
#define B_SZ  4
#define SEQ   4096
#define HIDN  1024
#define NH    16
#define HD    64
#define MTOT  (B_SZ * SEQ)   // 16384 tokens
#define MK    ((size_t)MTOT * HIDN)

// Arch-feature gate: tcgen05/TMEM only legal in arch-specific ('a') passes.
#if defined(__CUDA_ARCH__) && (defined(__CUDA_ARCH_FEAT_SM103_ALL) || defined(__CUDA_ARCH_FEAT_SM100_ALL) || defined(__CUDA_ARCH_FEAT_SM101_ALL))
#define HAS_TC 1
#else
#define HAS_TC 0
#endif

// Scratch (device globals: no allocations allowed in kernel_launch)
static __device__ float g_q[MK];
static __device__ float g_k[MK];
static __device__ float g_v[MK];
static __device__ float g_x[MK];                       // fp32 x (fallback path)
static __device__ __nv_bfloat16 g_ah[3 * MK];          // split activations hi (q,k,v inputs)
static __device__ __nv_bfloat16 g_al[3 * MK];          // split activations lo
static __device__ __nv_bfloat16 g_xh[MK];              // attention output hi (permuted)
static __device__ __nv_bfloat16 g_xl[MK];              // attention output lo
static __device__ __nv_bfloat16 g_wbh[4 * (size_t)HIDN * HIDN]; // weights^T hi [4][N][K]
static __device__ __nv_bfloat16 g_wbl[4 * (size_t)HIDN * HIDN]; // weights^T lo

// ===========================================================================
// GEMM tile geometry: 128x256 tile, BK=64, SS-mode, everything pre-split bf16
// ===========================================================================
#define GBM 128
#define GBN 256
#define GBK 64
#define GKD 1024
#define GNCH (GKD / GBK)          // 16 stages

#define SM_TMEM   0
#define SM_MBAR   8               // 2 mbarriers at 8,16
#define SM_BUF    1024
#define BUF_STRIDE 98304          // 96 KB/stage: AH 16K | AL 16K | BH 32K | BL 32K
#define OFF_AH 0
#define OFF_AL 16384
#define OFF_BH 32768
#define OFF_BL 65536
#define GEMM_SMEM_BYTES (1024 + 2 * BUF_STRIDE)   // 197632

// idesc: dtype=F32(1)<<4 | atype=BF16(1)<<7 | btype=BF16(1)<<10 | (N/8)<<17 | (M/16)<<24
#define IDESC_BF16 ((1u << 4) | (1u << 7) | (1u << 10) | ((GBN / 8) << 17) | ((GBM / 16) << 24))

extern __shared__ char dynsmem[];

#if HAS_TC
// ---------------------------------------------------------------------------
// tcgen05 helpers (arch-specific pass only)
// ---------------------------------------------------------------------------
__device__ __forceinline__ uint32_t s2u(const void* p) {
    uint32_t a;
    asm("{ .reg .u64 t; cvta.to.shared.u64 t, %1; cvt.u32.u64 %0, t; }"
        : "=r"(a) : "l"(p));
    return a;
}
__device__ __forceinline__ uint64_t to_global(const void* p) {
    uint64_t g;
    asm("cvta.to.global.u64 %0, %1;" : "=l"(g) : "l"(p));
    return g;
}
__device__ __forceinline__ bool elect1() {
    uint32_t p;
    asm volatile("{ .reg .pred p; elect.sync _|p, 0xFFFFFFFF; selp.b32 %0, 1, 0, p; }"
                 : "=r"(p));
    return p != 0;
}
__device__ __forceinline__ void mbar_init(uint32_t mbar, uint32_t cnt) {
    asm volatile("mbarrier.init.shared.b64 [%0], %1;" :: "r"(mbar), "r"(cnt) : "memory");
}
__device__ __forceinline__ void mbar_wait(uint32_t mbar, uint32_t parity) {
    asm volatile(
        "{\n\t"
        ".reg .pred P;\n\t"
        "WL%=:\n\t"
        "mbarrier.try_wait.parity.acquire.cta.shared::cta.b64 P, [%0], %1, 0x989680;\n\t"
        "@P bra.uni WD%=;\n\t"
        "bra.uni WL%=;\n\t"
        "WD%=:\n\t"
        "}"
        :: "r"(mbar), "r"(parity) : "memory");
}
__device__ __forceinline__ void tmem_alloc(uint32_t smem_dst, uint32_t ncols) {
    asm volatile("tcgen05.alloc.cta_group::1.sync.aligned.shared::cta.b32 [%0], %1;"
                 :: "r"(smem_dst), "r"(ncols) : "memory");
}
__device__ __forceinline__ void tmem_relinquish() {
    asm volatile("tcgen05.relinquish_alloc_permit.cta_group::1.sync.aligned;");
}
__device__ __forceinline__ void tmem_dealloc(uint32_t tmem, uint32_t ncols) {
    asm volatile("tcgen05.dealloc.cta_group::1.sync.aligned.b32 %0, %1;"
                 :: "r"(tmem), "r"(ncols));
}
__device__ __forceinline__ void tc_commit(uint32_t mbar) {
    asm volatile("tcgen05.commit.cta_group::1.mbarrier::arrive::one.shared::cluster.b64 [%0];"
                 :: "r"(mbar) : "memory");
}
__device__ __forceinline__ void tc_fence_after() {
    asm volatile("tcgen05.fence::after_thread_sync;" ::: "memory");
}
__device__ __forceinline__ void fence_async_smem() {
    asm volatile("fence.proxy.async.shared::cta;" ::: "memory");
}
__device__ __forceinline__ void tc_wait_ld() {
    asm volatile("tcgen05.wait::ld.sync.aligned;" ::: "memory");
}
__device__ __forceinline__ void cp16(uint32_t dst_smem, uint64_t src_gmem) {
    asm volatile("cp.async.cg.shared.global [%0], [%1], 16;"
                 :: "r"(dst_smem), "l"(src_gmem) : "memory");
}
__device__ __forceinline__ void cp_commit() {
    asm volatile("cp.async.commit_group;" ::: "memory");
}
__device__ __forceinline__ void cp_wait0() {
    asm volatile("cp.async.wait_group 0;" ::: "memory");
}

// SS bf16 MMA, cta_group::1
__device__ __forceinline__ void mma_bf16(uint32_t d_tmem, uint64_t a_desc,
                                         uint64_t b_desc, uint32_t idesc, uint32_t en) {
    asm volatile(
        "{\n\t"
        ".reg .pred p;\n\t"
        "setp.ne.u32 p, %4, 0;\n\t"
        "tcgen05.mma.cta_group::1.kind::f16 [%0], %1, %2, %3, {%5, %5, %5, %5}, p;\n\t"
        "}"
        :: "r"(d_tmem), "l"(a_desc), "l"(b_desc), "r"(idesc), "r"(en), "r"(0u)
        : "memory");
}

#define TC_LD_X32(r, addr)                                                     \
    asm volatile(                                                              \
        "tcgen05.ld.sync.aligned.32x32b.x32.b32 "                              \
        "{%0, %1, %2, %3, %4, %5, %6, %7, "                                    \
        " %8, %9, %10, %11, %12, %13, %14, %15, "                              \
        " %16, %17, %18, %19, %20, %21, %22, %23, "                            \
        " %24, %25, %26, %27, %28, %29, %30, %31}, [%32];"                     \
        : "=r"((r)[0]),  "=r"((r)[1]),  "=r"((r)[2]),  "=r"((r)[3]),           \
          "=r"((r)[4]),  "=r"((r)[5]),  "=r"((r)[6]),  "=r"((r)[7]),           \
          "=r"((r)[8]),  "=r"((r)[9]),  "=r"((r)[10]), "=r"((r)[11]),          \
          "=r"((r)[12]), "=r"((r)[13]), "=r"((r)[14]), "=r"((r)[15]),          \
          "=r"((r)[16]), "=r"((r)[17]), "=r"((r)[18]), "=r"((r)[19]),          \
          "=r"((r)[20]), "=r"((r)[21]), "=r"((r)[22]), "=r"((r)[23]),          \
          "=r"((r)[24]), "=r"((r)[25]), "=r"((r)[26]), "=r"((r)[27]),          \
          "=r"((r)[28]), "=r"((r)[29]), "=r"((r)[30]), "=r"((r)[31])           \
        : "r"(addr))

#define SWZ(o) ((o) ^ (((o) >> 3) & 0x70))

// SW128 descriptor: layout=2<<61 | version=1<<46 | SBO=64<<32 | LBO=1<<16
__device__ __forceinline__ uint64_t mkdesc(uint32_t smem_addr) {
    return 0x4000404000010000ull | ((uint64_t)(smem_addr >> 4) & 0x3FFF);
}

// Issue all cp.async for stage kt into slot kt&1 (A hi/lo + B hi/lo; 24/thread).
__device__ __forceinline__ void issue_cp(uint32_t sb, uint64_t ahg, uint64_t alg,
                                         uint64_t whg, uint64_t wlg,
                                         int row0, int col0, int kt, int tid) {
    const uint32_t bufu = sb + SM_BUF + (kt & 1) * BUF_STRIDE;
    const int kbase = kt * GBK;
#pragma unroll
    for (int j = 0; j < 4; j++) {                 // A: 128 rows x 8 granules/plane
        const int c = tid + 256 * j;
        const int r = c >> 3, k8 = c & 7;
        const uint64_t so = ((uint64_t)(row0 + r) * GKD + kbase + k8 * 8) * 2;
        const uint32_t doff = SWZ((uint32_t)(r * 128 + k8 * 16));
        cp16(bufu + OFF_AH + doff, ahg + so);
        cp16(bufu + OFF_AL + doff, alg + so);
    }
#pragma unroll
    for (int j = 0; j < 8; j++) {                 // B: 256 rows x 8 granules/plane
        const int c = tid + 256 * j;
        const int n = c >> 3, k8 = c & 7;
        const uint64_t so = ((uint64_t)(col0 + n) * GKD + kbase + k8 * 8) * 2;
        const uint32_t doff = SWZ((uint32_t)(n * 128 + k8 * 16));
        cp16(bufu + OFF_BH + doff, whg + so);
        cp16(bufu + OFF_BL + doff, wlg + so);
    }
    cp_commit();
}

// ---------------------------------------------------------------------------
// GEMM core: C[128,256 tile] = (Ah+Al) @ (Wh+Wl)^T (3-term split) + bias.
// Pipelined so MMA(kt) overlaps the refill of slot (kt+1)&1:
//   iter kt:  [cp(kt) resident] -> issue MMA(kt) -> wait MMA(kt-1) -> cp(kt+1)
// MMA(kt-1) read slot (kt+1)&1, so the refill is safe, and the wait is cheap
// because MMA(kt-1) retires while MMA(kt) occupies the tensor pipe.
// ---------------------------------------------------------------------------
__device__ __forceinline__ void gemm_core(const __nv_bfloat16* __restrict__ Ah,
                                          const __nv_bfloat16* __restrict__ Al,
                                          const __nv_bfloat16* __restrict__ Wh,
                                          const __nv_bfloat16* __restrict__ Wl,
                                          const float* __restrict__ bias,
                                          float* __restrict__ C)
{
    const uint32_t sb = s2u(dynsmem);
    const int tid  = threadIdx.x;
    const int row0 = blockIdx.y * GBM;
    const int col0 = blockIdx.x * GBN;

    if (tid < 32) {
        tmem_alloc(sb + SM_TMEM, 256);
        tmem_relinquish();
    }
    if (tid == 0) {
        mbar_init(sb + SM_MBAR + 0, 1);
        mbar_init(sb + SM_MBAR + 8, 1);
    }
    __syncthreads();

    uint32_t tmem;
    asm volatile("ld.shared.b32 %0, [%1];" : "=r"(tmem) : "r"(sb + SM_TMEM));

    const uint64_t ahg = to_global(Ah);
    const uint64_t alg = to_global(Al);
    const uint64_t whg = to_global(Wh);
    const uint64_t wlg = to_global(Wl);

    // Prologue: stage 0 in flight.
    issue_cp(sb, ahg, alg, whg, wlg, row0, col0, 0, tid);

#pragma unroll 1
    for (int kt = 0; kt < GNCH; kt++) {
        // cp(kt) must be resident (it is the only outstanding group here).
        cp_wait0();
        fence_async_smem();
        __syncthreads();

        // 12 MMAs: (hh, hl, lh) x 4 k-steps; commit to this stage's mbar.
        if (tid < 32) {
            if (elect1()) {
                const uint32_t bufu = sb + SM_BUF + (kt & 1) * BUF_STRIDE;
                const uint64_t dAh = mkdesc(bufu + OFF_AH);
                const uint64_t dAl = mkdesc(bufu + OFF_AL);
                const uint64_t dBh = mkdesc(bufu + OFF_BH);
                const uint64_t dBl = mkdesc(bufu + OFF_BL);
#pragma unroll
                for (int ks = 0; ks < 4; ks++)
                    mma_bf16(tmem, dAh + 2 * ks, dBh + 2 * ks, IDESC_BF16,
                             (kt == 0 && ks == 0) ? 0u : 1u);
#pragma unroll
                for (int ks = 0; ks < 4; ks++)
                    mma_bf16(tmem, dAh + 2 * ks, dBl + 2 * ks, IDESC_BF16, 1u);
#pragma unroll
                for (int ks = 0; ks < 4; ks++)
                    mma_bf16(tmem, dAl + 2 * ks, dBh + 2 * ks, IDESC_BF16, 1u);
                tc_commit(sb + SM_MBAR + (kt & 1) * 8);
            }
        }

        // Refill slot (kt+1)&1 once MMA(kt-1) (its previous reader) is done.
        if (kt + 1 < GNCH) {
            if (kt >= 1)
                mbar_wait(sb + SM_MBAR + ((kt - 1) & 1) * 8,
                          (uint32_t)(((kt - 1) >> 1) & 1));
            issue_cp(sb, ahg, alg, whg, wlg, row0, col0, kt + 1, tid);
        }
    }

    // Drain the final MMA batch (commit tracks all prior MMAs).
    {
        const int kt = GNCH - 1;
        mbar_wait(sb + SM_MBAR + (kt & 1) * 8, (uint32_t)((kt >> 1) & 1));
    }
    tc_fence_after();

    // Epilogue: warps 0-3 read D from TMEM, add bias, store.
    if (tid < 128) {
        const int m = row0 + tid;
        float* Crow = C + (size_t)m * HIDN + col0;
#pragma unroll
        for (int n0 = 0; n0 < GBN; n0 += 32) {
            uint32_t r[32];
            TC_LD_X32(r, tmem + n0);
            tc_wait_ld();
#pragma unroll
            for (int j = 0; j < 32; j += 4) {
                float4 o;
                o.x = __uint_as_float(r[j + 0]) + bias[col0 + n0 + j + 0];
                o.y = __uint_as_float(r[j + 1]) + bias[col0 + n0 + j + 1];
                o.z = __uint_as_float(r[j + 2]) + bias[col0 + n0 + j + 2];
                o.w = __uint_as_float(r[j + 3]) + bias[col0 + n0 + j + 3];
                *(float4*)(Crow + n0 + j) = o;
            }
        }
    }
    __syncthreads();
    if (tid < 32) tmem_dealloc(tmem, 256);
}
#endif  // HAS_TC

// Merged QKV GEMM (z selects pre-split input/weight/bias/output).
__global__ __launch_bounds__(256, 1)
void gemm_qkv(const __nv_bfloat16* __restrict__ ah, const __nv_bfloat16* __restrict__ al,
              const __nv_bfloat16* __restrict__ wh, const __nv_bfloat16* __restrict__ wl,
              const float* __restrict__ bq, const float* __restrict__ bk,
              const float* __restrict__ bv,
              float* __restrict__ oq, float* __restrict__ ok, float* __restrict__ ov)
{
#if HAS_TC
    const int z = blockIdx.z;
    const float* bias = (z == 0) ? bq : (z == 1) ? bk : bv;
    float* C = (z == 0) ? oq : (z == 1) ? ok : ov;
    const size_t ao = (size_t)z * MK;
    const size_t wo = (size_t)z * HIDN * HIDN;
    gemm_core(ah + ao, al + ao, wh + wo, wl + wo, bias, C);
#endif
}

// Single GEMM (output projection; also the runtime capability probe).
__global__ __launch_bounds__(256, 1)
void gemm_single(const __nv_bfloat16* __restrict__ ah, const __nv_bfloat16* __restrict__ al,
                 const __nv_bfloat16* __restrict__ wh, const __nv_bfloat16* __restrict__ wl,
                 const float* __restrict__ bias, float* __restrict__ C)
{
#if HAS_TC
    gemm_core(ah, al, wh, wl, bias, C);
#endif
}

// ===========================================================================
// Activation split: fp32 q/k/v -> bf16 hi/lo (z selects source matrix).
// ===========================================================================
__global__ __launch_bounds__(256)
void split_acts(const float* __restrict__ q, const float* __restrict__ k,
                const float* __restrict__ v,
                __nv_bfloat16* __restrict__ ah, __nv_bfloat16* __restrict__ al)
{
    const int z = blockIdx.z;
    const float* src = (z == 0) ? q : (z == 1) ? k : v;
    __nv_bfloat16* dh = ah + (size_t)z * MK;
    __nv_bfloat16* dl = al + (size_t)z * MK;
    const size_t i = ((size_t)blockIdx.x * 256 + threadIdx.x) * 4;
    const float4 x = *(const float4*)(src + i);
    __nv_bfloat162 h0 = __floats2bfloat162_rn(x.x, x.y);
    __nv_bfloat162 h1 = __floats2bfloat162_rn(x.z, x.w);
    const float2 f0 = __bfloat1622float2(h0);
    const float2 f1 = __bfloat1622float2(h1);
    __nv_bfloat162 l0 = __floats2bfloat162_rn(x.x - f0.x, x.y - f0.y);
    __nv_bfloat162 l1 = __floats2bfloat162_rn(x.z - f1.x, x.w - f1.y);
    *(uint2*)(dh + i) = make_uint2(*(uint32_t*)&h0, *(uint32_t*)&h1);
    *(uint2*)(dl + i) = make_uint2(*(uint32_t*)&l0, *(uint32_t*)&l1);
}

// ===========================================================================
// Weight prep: WTh[n][k] = bf16(W[k][n]), WTl = bf16(residual). 4 matrices.
// ===========================================================================
__global__ __launch_bounds__(256)
void prep_weights(const float* __restrict__ s0, const float* __restrict__ s1,
                  const float* __restrict__ s2, const float* __restrict__ s3,
                  __nv_bfloat16* __restrict__ dh, __nv_bfloat16* __restrict__ dl)
{
    __shared__ float t[32][33];
    const float* src = (blockIdx.z == 0) ? s0 : (blockIdx.z == 1) ? s1
                     : (blockIdx.z == 2) ? s2 : s3;
    const size_t zo = (size_t)blockIdx.z * HIDN * HIDN;
    const int x0 = blockIdx.x * 32, y0 = blockIdx.y * 32;   // x: n, y: k
    const int tx = threadIdx.x & 31, ty0 = threadIdx.x >> 5;
#pragma unroll
    for (int i = 0; i < 4; i++) {
        const int ty = ty0 + i * 8;
        t[ty][tx] = src[(size_t)(y0 + ty) * HIDN + x0 + tx];
    }
    __syncthreads();
#pragma unroll
    for (int i = 0; i < 4; i++) {
        const int ty = ty0 + i * 8;
        const float val = t[tx][ty];
        const __nv_bfloat16 h = __float2bfloat16_rn(val);
        const __nv_bfloat16 l = __float2bfloat16_rn(val - __bfloat162float(h));
        const size_t di = zo + (size_t)(x0 + ty) * HIDN + (y0 + tx);
        dh[di] = h;
        dl[di] = l;
    }
}

// ===========================================================================
// Fallback SGEMM (fp32, proven path) — compiles on every arch.
// ===========================================================================
#define BM 128
#define BN 128
#define BK 16

__global__ __launch_bounds__(256, 2)
void sgemm_bias(const float* __restrict__ A, const float* __restrict__ W,
                const float* __restrict__ bias, float* __restrict__ C,
                int M, int N, int K)
{
    __shared__ float As[2][BK][BM];
    __shared__ float Bs[2][BK][BN];

    const int tid = threadIdx.x;
    const int tx  = tid & 15;
    const int ty  = tid >> 4;
    const int row0 = blockIdx.y * BM;
    const int col0 = blockIdx.x * BN;

    const int a_r = tid >> 2;
    const int a_k = (tid & 3) << 2;
    const int b_r = tid >> 5;
    const int b_c = (tid & 31) << 2;

    const float* Ab = A + (size_t)row0 * K;

    float acc[8][8];
#pragma unroll
    for (int i = 0; i < 8; i++)
#pragma unroll
        for (int j = 0; j < 8; j++) acc[i][j] = 0.f;

    {
        float4 a0 = *(const float4*)(Ab + (size_t)a_r * K + a_k);
        float4 a1 = *(const float4*)(Ab + (size_t)(a_r + 64) * K + a_k);
        float4 w0 = *(const float4*)(W + (size_t)b_r * N + col0 + b_c);
        float4 w1 = *(const float4*)(W + (size_t)(b_r + 8) * N + col0 + b_c);
        As[0][a_k + 0][a_r] = a0.x; As[0][a_k + 1][a_r] = a0.y;
        As[0][a_k + 2][a_r] = a0.z; As[0][a_k + 3][a_r] = a0.w;
        As[0][a_k + 0][a_r + 64] = a1.x; As[0][a_k + 1][a_r + 64] = a1.y;
        As[0][a_k + 2][a_r + 64] = a1.z; As[0][a_k + 3][a_r + 64] = a1.w;
        *(float4*)&Bs[0][b_r][b_c]     = w0;
        *(float4*)&Bs[0][b_r + 8][b_c] = w1;
    }
    __syncthreads();

    const int NT = K / BK;
    for (int kt = 0; kt < NT; kt++) {
        const int cur = kt & 1;

        float4 a0, a1, w0, w1;
        const bool more = (kt + 1 < NT);
        if (more) {
            const float* Ap = Ab + (size_t)(kt + 1) * BK;
            a0 = *(const float4*)(Ap + (size_t)a_r * K + a_k);
            a1 = *(const float4*)(Ap + (size_t)(a_r + 64) * K + a_k);
            const float* Wp = W + (size_t)(kt + 1) * BK * N + col0;
            w0 = *(const float4*)(Wp + (size_t)b_r * N + b_c);
            w1 = *(const float4*)(Wp + (size_t)(b_r + 8) * N + b_c);
        }

#pragma unroll
        for (int kk = 0; kk < BK; kk++) {
            float ar[8], br[8];
            *(float4*)(ar)     = *(const float4*)&As[cur][kk][ty * 8];
            *(float4*)(ar + 4) = *(const float4*)&As[cur][kk][ty * 8 + 4];
            *(float4*)(br)     = *(const float4*)&Bs[cur][kk][tx * 8];
            *(float4*)(br + 4) = *(const float4*)&Bs[cur][kk][tx * 8 + 4];
#pragma unroll
            for (int i = 0; i < 8; i++)
#pragma unroll
                for (int j = 0; j < 8; j++)
                    acc[i][j] += ar[i] * br[j];
        }

        if (more) {
            const int nxt = cur ^ 1;
            As[nxt][a_k + 0][a_r] = a0.x; As[nxt][a_k + 1][a_r] = a0.y;
            As[nxt][a_k + 2][a_r] = a0.z; As[nxt][a_k + 3][a_r] = a0.w;
            As[nxt][a_k + 0][a_r + 64] = a1.x; As[nxt][a_k + 1][a_r + 64] = a1.y;
            As[nxt][a_k + 2][a_r + 64] = a1.z; As[nxt][a_k + 3][a_r + 64] = a1.w;
            *(float4*)&Bs[nxt][b_r][b_c]     = w0;
            *(float4*)&Bs[nxt][b_r + 8][b_c] = w1;
        }
        __syncthreads();
    }

#pragma unroll
    for (int i = 0; i < 8; i++) {
        const size_t r = (size_t)(row0 + ty * 8 + i);
#pragma unroll
        for (int j4 = 0; j4 < 8; j4 += 4) {
            const int c = col0 + tx * 8 + j4;
            float4 o;
            o.x = acc[i][j4 + 0] + bias[c + 0];
            o.y = acc[i][j4 + 1] + bias[c + 1];
            o.z = acc[i][j4 + 2] + bias[c + 2];
            o.w = acc[i][j4 + 3] + bias[c + 3];
            *(float4*)&C[r * N + c] = o;
        }
    }
}

// ===========================================================================
// Per-token attention over the HEADS axis. float4-vectorized LDS; output
// written either fp32 (fallback) or pre-split bf16 hi/lo (tensor path).
// Reg-capped to recover the occupancy lost in R9.
// ===========================================================================
#define PD 68

__global__ __launch_bounds__(256, 5)
void attn_kernel(const float* __restrict__ q, const float* __restrict__ k,
                 const float* __restrict__ v, const float* __restrict__ sw,
                 float* __restrict__ xf,
                 __nv_bfloat16* __restrict__ xh, __nv_bfloat16* __restrict__ xl,
                 float* __restrict__ attn_out, int write_attn, int out_bf16)
{
    __shared__ float sq[NH][PD], sk[NH][PD], sv[NH][PD];
    __shared__ float s_qk[NH][NH];
    __shared__ float s_qn2[NH], s_kn2[NH];
    __shared__ float s_at[NH][NH + 1];

    const int t   = blockIdx.x;
    const int b   = t >> 12;
    const int s   = t & 4095;
    const int tid = threadIdx.x;
    const size_t base = (size_t)t * HIDN;

    {
        const int row = tid >> 4;
        const int col = (tid & 15) << 2;
        *(float4*)&sq[row][col] = *(const float4*)(q + base + row * HD + col);
        *(float4*)&sk[row][col] = *(const float4*)(k + base + row * HD + col);
        *(float4*)&sv[row][col] = *(const float4*)(v + base + row * HD + col);
    }
    __syncthreads();

    if (tid < 32) {
        const int i = tid & 15;
        const float* p = (tid < 16) ? sq[i] : sk[i];
        float ss = 0.f;
#pragma unroll
        for (int d4 = 0; d4 < 16; d4++) {
            const float4 a = *(const float4*)(p + d4 * 4);
            ss += a.x * a.x + a.y * a.y + a.z * a.z + a.w * a.w;
        }
        if (tid < 16) s_qn2[i] = ss; else s_kn2[i] = ss;
    }
    {
        const int i = tid >> 4, j = tid & 15;
        float dot = 0.f;
#pragma unroll
        for (int d4 = 0; d4 < 16; d4++) {
            const float4 a = *(const float4*)&sq[i][d4 * 4];
            const float4 c = *(const float4*)&sk[j][d4 * 4];
            dot += a.x * c.x + a.y * c.y + a.z * c.z + a.w * c.w;
        }
        s_qk[i][j] = dot;
    }
    __syncthreads();

    if (tid < NH) {
        float w0, w1, w2;
        {
            const float x0 = sw[0], x1 = sw[1], x2 = sw[2];
            const float m  = fmaxf(x0, fmaxf(x1, x2));
            const float e0 = expf(x0 - m), e1 = expf(x1 - m), e2 = expf(x2 - m);
            const float inv = 1.f / (e0 + e1 + e2);
            w0 = e0 * inv; w1 = e1 * inv; w2 = e2 * inv;
        }
        const int i = tid;
        const float qn2 = s_qn2[i];
        const float qn  = sqrtf(qn2);
        float sc[NH];
        float mx = -1e30f;
#pragma unroll
        for (int j = 0; j < NH; j++) {
            const float qkv  = s_qk[i][j];
            const float kn2  = s_kn2[j];
            const float dotv = qkv * 0.125f;
            const float cosv = qkv / fmaxf(qn * sqrtf(kn2), 1e-8f);
            const float d2   = fmaxf(qn2 + kn2 - 2.f * qkv, 0.f);
            const float dstv = -sqrtf(d2);
            const float scv  = w0 * dotv + w1 * cosv + w2 * dstv;
            sc[j] = scv;
            mx = fmaxf(mx, scv);
        }
        float ssum = 0.f;
#pragma unroll
        for (int j = 0; j < NH; j++) { const float e = expf(sc[j] - mx); sc[j] = e; ssum += e; }
        const float inv = 1.f / ssum;
#pragma unroll
        for (int j = 0; j < NH; j++) {
            const float a = sc[j] * inv;
            s_at[i][j] = a;
            if (write_attn)
                attn_out[(size_t)t * (NH * NH) + i * NH + j] = a;
        }
    }
    __syncthreads();

    {
        const int i  = tid >> 4;
        const int db = (tid & 15) << 2;
        float4 o = make_float4(0.f, 0.f, 0.f, 0.f);
#pragma unroll
        for (int j = 0; j < NH; j++) {
            const float a = s_at[i][j];
            const float4 vv = *(const float4*)&sv[j][db];
            o.x += a * vv.x; o.y += a * vv.y; o.z += a * vv.z; o.w += a * vv.w;
        }
        // transpose(1,2).reshape fold: row = h*256 + s/16, col = (s%16)*64 + d
        const size_t dst = (size_t)b * ((size_t)SEQ * HIDN)
                         + (size_t)((i << 8) + (s >> 4)) * HIDN
                         + (size_t)((s & 15) << 6) + db;
        if (out_bf16) {
            __nv_bfloat162 h0 = __floats2bfloat162_rn(o.x, o.y);
            __nv_bfloat162 h1 = __floats2bfloat162_rn(o.z, o.w);
            const float2 f0 = __bfloat1622float2(h0);
            const float2 f1 = __bfloat1622float2(h1);
            __nv_bfloat162 l0 = __floats2bfloat162_rn(o.x - f0.x, o.y - f0.y);
            __nv_bfloat162 l1 = __floats2bfloat162_rn(o.z - f1.x, o.w - f1.y);
            *(uint2*)(xh + dst) = make_uint2(*(uint32_t*)&h0, *(uint32_t*)&h1);
            *(uint2*)(xl + dst) = make_uint2(*(uint32_t*)&l0, *(uint32_t*)&l1);
        } else {
            *(float4*)&xf[dst] = o;
        }
    }
}

// ===========================================================================
extern "C" void kernel_launch(void* const* d_in, const int* in_sizes, int n_in,
                              void* d_out, int out_size)
{
    const float* query = (const float*)d_in[0];
    const float* key_  = (const float*)d_in[1];
    const float* value = (const float*)d_in[2];
    const float* Wq    = (const float*)d_in[3];
    const float* bq    = (const float*)d_in[4];
    const float* Wk    = (const float*)d_in[5];
    const float* bk    = (const float*)d_in[6];
    const float* Wv    = (const float*)d_in[7];
    const float* bv    = (const float*)d_in[8];
    const float* Wo    = (const float*)d_in[9];
    const float* bo    = (const float*)d_in[10];
    const float* sw    = (const float*)d_in[11];
    float* out = (float*)d_out;

    float *gq, *gk, *gv, *gx;
    __nv_bfloat16 *gah, *gal, *gxh, *gxl, *gwh, *gwl;
    cudaGetSymbolAddress((void**)&gq,  g_q);
    cudaGetSymbolAddress((void**)&gk,  g_k);
    cudaGetSymbolAddress((void**)&gv,  g_v);
    cudaGetSymbolAddress((void**)&gx,  g_x);
    cudaGetSymbolAddress((void**)&gah, g_ah);
    cudaGetSymbolAddress((void**)&gal, g_al);
    cudaGetSymbolAddress((void**)&gxh, g_xh);
    cudaGetSymbolAddress((void**)&gxl, g_xl);
    cudaGetSymbolAddress((void**)&gwh, g_wbh);
    cudaGetSymbolAddress((void**)&gwl, g_wbl);

    const long long main_elems = (long long)MTOT * HIDN;
    const long long attn_elems = (long long)MTOT * NH * NH;
    const int write_attn = ((long long)out_size >= main_elems + attn_elems) ? 1 : 0;
    float* attn_ptr = out + main_elems;

    // Capability probe: stubbed (non-'a' pass) kernel uses only a few regs.
    cudaFuncAttributes fa;
    fa.numRegs = 0;
    cudaError_t perr = cudaFuncGetAttributes(&fa, gemm_single);
    const bool use_tc = (perr == cudaSuccess) && (fa.numRegs >= 24);

    if (use_tc) {
        cudaFuncSetAttribute(gemm_qkv, cudaFuncAttributeMaxDynamicSharedMemorySize,
                             GEMM_SMEM_BYTES);
        cudaFuncSetAttribute(gemm_single, cudaFuncAttributeMaxDynamicSharedMemorySize,
                             GEMM_SMEM_BYTES);

        // Prep: transpose+split weights; split activations.
        prep_weights<<<dim3(32, 32, 4), 256>>>(Wq, Wk, Wv, Wo, gwh, gwl);
        split_acts<<<dim3(MTOT * HIDN / 1024, 1, 3), 256>>>(query, key_, value, gah, gal);

        const size_t WSZ = (size_t)HIDN * HIDN;
        dim3 gq3(HIDN / GBN, MTOT / GBM, 3);   // (4, 128, 3)
        dim3 gg1(HIDN / GBN, MTOT / GBM);

        gemm_qkv<<<gq3, 256, GEMM_SMEM_BYTES>>>(gah, gal, gwh, gwl,
                                                bq, bk, bv, gq, gk, gv);

        attn_kernel<<<MTOT, 256>>>(gq, gk, gv, sw, gx, gxh, gxl,
                                   attn_ptr, write_attn, 1);

        gemm_single<<<gg1, 256, GEMM_SMEM_BYTES>>>(gxh, gxl, gwh + 3 * WSZ,
                                                   gwl + 3 * WSZ, bo, out);
    } else {
        // Fallback: proven fp32 path.
        dim3 gg(HIDN / BN, MTOT / BM);
        sgemm_bias<<<gg, 256>>>(query, Wq, bq, gq, MTOT, HIDN, HIDN);
        sgemm_bias<<<gg, 256>>>(key_,  Wk, bk, gk, MTOT, HIDN, HIDN);
        sgemm_bias<<<gg, 256>>>(value, Wv, bv, gv, MTOT, HIDN, HIDN);

        attn_kernel<<<MTOT, 256>>>(gq, gk, gv, sw, gx, nullptr, nullptr,
                                   attn_ptr, write_attn, 0);

        sgemm_bias<<<gg, 256>>>(gx, Wo, bo, out, MTOT, HIDN, HIDN);
    }
}

// round 14
// speedup vs baseline: 1.1735x; 1.1647x over previous
#include <cuda_runtime.h>
#include <cuda_bf16.h>
#include <cstdint>

// Problem constants
#define B_SZ  4
#define SEQ   4096
#define HIDN  1024
#define NH    16
#define HD    64
#define MTOT  (B_SZ * SEQ)   // 16384 tokens
#define MK    ((size_t)MTOT * HIDN)

// Arch-feature gate: tcgen05/TMEM only legal in arch-specific ('a') passes.
#if defined(__CUDA_ARCH__) && (defined(__CUDA_ARCH_FEAT_SM103_ALL) || defined(__CUDA_ARCH_FEAT_SM100_ALL) || defined(__CUDA_ARCH_FEAT_SM101_ALL))
#define HAS_TC 1
#else
#define HAS_TC 0
#endif

// Scratch (device globals: no allocations allowed in kernel_launch)
static __device__ float g_q[MK];
static __device__ float g_k[MK];
static __device__ float g_v[MK];
static __device__ float g_x[MK];                       // fp32 x (fallback path)
static __device__ __nv_bfloat16 g_ah[3 * MK];          // split activations hi (q,k,v inputs)
static __device__ __nv_bfloat16 g_al[3 * MK];          // split activations lo
static __device__ __nv_bfloat16 g_xh[MK];              // attention output hi (permuted)
static __device__ __nv_bfloat16 g_xl[MK];              // attention output lo
static __device__ __nv_bfloat16 g_wbh[4 * (size_t)HIDN * HIDN]; // weights^T hi [4][N][K]
static __device__ __nv_bfloat16 g_wbl[4 * (size_t)HIDN * HIDN]; // weights^T lo

// ===========================================================================
// GEMM tile geometry: 256x256 tile, BK=32 (SW64), SS-mode, pre-split bf16.
// Two M=128 MMA batches per stage (D at TMEM cols 0 and 256).
// ===========================================================================
#define GBM 256
#define GBN 256
#define GBK 32
#define GKD 1024
#define GNCH (GKD / GBK)          // 32 stages

#define NSTG 3
#define SM_TMEM   0
#define SM_MBAR   8               // 3 mbarriers at 8,16,24
#define SM_BUF    1024
#define BUF_STRIDE 65536          // 64 KB/stage: AH 16K | AL 16K | BH 16K | BL 16K
#define OFF_AH 0
#define OFF_AL 16384
#define OFF_BH 32768
#define OFF_BL 49152
#define GEMM_SMEM_BYTES (1024 + NSTG * BUF_STRIDE)   // 197632

// idesc: dtype=F32(1)<<4 | atype=BF16(1)<<7 | btype=BF16(1)<<10 | (N/8)<<17 | (M/16)<<24
#define IDESC_BF16 ((1u << 4) | (1u << 7) | (1u << 10) | ((GBN / 8) << 17) | ((128 / 16) << 24))

extern __shared__ char dynsmem[];

#if HAS_TC
// ---------------------------------------------------------------------------
// tcgen05 helpers (arch-specific pass only)
// ---------------------------------------------------------------------------
__device__ __forceinline__ uint32_t s2u(const void* p) {
    uint32_t a;
    asm("{ .reg .u64 t; cvta.to.shared.u64 t, %1; cvt.u32.u64 %0, t; }"
        : "=r"(a) : "l"(p));
    return a;
}
__device__ __forceinline__ uint64_t to_global(const void* p) {
    uint64_t g;
    asm("cvta.to.global.u64 %0, %1;" : "=l"(g) : "l"(p));
    return g;
}
__device__ __forceinline__ bool elect1() {
    uint32_t p;
    asm volatile("{ .reg .pred p; elect.sync _|p, 0xFFFFFFFF; selp.b32 %0, 1, 0, p; }"
                 : "=r"(p));
    return p != 0;
}
__device__ __forceinline__ void mbar_init(uint32_t mbar, uint32_t cnt) {
    asm volatile("mbarrier.init.shared.b64 [%0], %1;" :: "r"(mbar), "r"(cnt) : "memory");
}
__device__ __forceinline__ void mbar_wait(uint32_t mbar, uint32_t parity) {
    asm volatile(
        "{\n\t"
        ".reg .pred P;\n\t"
        "WL%=:\n\t"
        "mbarrier.try_wait.parity.acquire.cta.shared::cta.b64 P, [%0], %1, 0x989680;\n\t"
        "@P bra.uni WD%=;\n\t"
        "bra.uni WL%=;\n\t"
        "WD%=:\n\t"
        "}"
        :: "r"(mbar), "r"(parity) : "memory");
}
__device__ __forceinline__ void tmem_alloc(uint32_t smem_dst, uint32_t ncols) {
    asm volatile("tcgen05.alloc.cta_group::1.sync.aligned.shared::cta.b32 [%0], %1;"
                 :: "r"(smem_dst), "r"(ncols) : "memory");
}
__device__ __forceinline__ void tmem_relinquish() {
    asm volatile("tcgen05.relinquish_alloc_permit.cta_group::1.sync.aligned;");
}
__device__ __forceinline__ void tmem_dealloc(uint32_t tmem, uint32_t ncols) {
    asm volatile("tcgen05.dealloc.cta_group::1.sync.aligned.b32 %0, %1;"
                 :: "r"(tmem), "r"(ncols));
}
__device__ __forceinline__ void tc_commit(uint32_t mbar) {
    asm volatile("tcgen05.commit.cta_group::1.mbarrier::arrive::one.shared::cluster.b64 [%0];"
                 :: "r"(mbar) : "memory");
}
__device__ __forceinline__ void tc_fence_after() {
    asm volatile("tcgen05.fence::after_thread_sync;" ::: "memory");
}
__device__ __forceinline__ void fence_async_smem() {
    asm volatile("fence.proxy.async.shared::cta;" ::: "memory");
}
__device__ __forceinline__ void tc_wait_ld() {
    asm volatile("tcgen05.wait::ld.sync.aligned;" ::: "memory");
}
__device__ __forceinline__ void cp16(uint32_t dst_smem, uint64_t src_gmem) {
    asm volatile("cp.async.cg.shared.global [%0], [%1], 16;"
                 :: "r"(dst_smem), "l"(src_gmem) : "memory");
}
__device__ __forceinline__ void cp_commit() {
    asm volatile("cp.async.commit_group;" ::: "memory");
}
__device__ __forceinline__ void cp_wait1() {
    asm volatile("cp.async.wait_group 1;" ::: "memory");
}

// SS bf16 MMA, cta_group::1
__device__ __forceinline__ void mma_bf16(uint32_t d_tmem, uint64_t a_desc,
                                         uint64_t b_desc, uint32_t idesc, uint32_t en) {
    asm volatile(
        "{\n\t"
        ".reg .pred p;\n\t"
        "setp.ne.u32 p, %4, 0;\n\t"
        "tcgen05.mma.cta_group::1.kind::f16 [%0], %1, %2, %3, {%5, %5, %5, %5}, p;\n\t"
        "}"
        :: "r"(d_tmem), "l"(a_desc), "l"(b_desc), "r"(idesc), "r"(en), "r"(0u)
        : "memory");
}

#define TC_LD_X32(r, addr)                                                     \
    asm volatile(                                                              \
        "tcgen05.ld.sync.aligned.32x32b.x32.b32 "                              \
        "{%0, %1, %2, %3, %4, %5, %6, %7, "                                    \
        " %8, %9, %10, %11, %12, %13, %14, %15, "                              \
        " %16, %17, %18, %19, %20, %21, %22, %23, "                            \
        " %24, %25, %26, %27, %28, %29, %30, %31}, [%32];"                     \
        : "=r"((r)[0]),  "=r"((r)[1]),  "=r"((r)[2]),  "=r"((r)[3]),           \
          "=r"((r)[4]),  "=r"((r)[5]),  "=r"((r)[6]),  "=r"((r)[7]),           \
          "=r"((r)[8]),  "=r"((r)[9]),  "=r"((r)[10]), "=r"((r)[11]),          \
          "=r"((r)[12]), "=r"((r)[13]), "=r"((r)[14]), "=r"((r)[15]),          \
          "=r"((r)[16]), "=r"((r)[17]), "=r"((r)[18]), "=r"((r)[19]),          \
          "=r"((r)[20]), "=r"((r)[21]), "=r"((r)[22]), "=r"((r)[23]),          \
          "=r"((r)[24]), "=r"((r)[25]), "=r"((r)[26]), "=r"((r)[27]),          \
          "=r"((r)[28]), "=r"((r)[29]), "=r"((r)[30]), "=r"((r)[31])           \
        : "r"(addr))

// SW64 swizzle: atom = 8 rows x 64B; bits[5:4] ^= bits[8:7]
#define SWZ64(o) ((o) ^ (((o) >> 3) & 0x30))

// SW64 descriptor: layout=4<<61 | version=1<<46 | SBO=32<<32 | LBO=1<<16
__device__ __forceinline__ uint64_t mkdesc64(uint32_t smem_addr) {
    return ((4ull << 61) | (1ull << 46) | (32ull << 32) | (1ull << 16))
         | ((uint64_t)(smem_addr >> 4) & 0x3FFF);
}

// Issue all cp.async for stage kt into slot kt%NSTG (16 granules/thread).
// Each plane: 256 rows x 32 bf16 (64B rows, SW64-swizzled), 1024 granules.
__device__ __forceinline__ void issue_cp(uint32_t sb, uint64_t ahg, uint64_t alg,
                                         uint64_t whg, uint64_t wlg,
                                         int row0, int col0, int kt, int tid) {
    const uint32_t bufu = sb + SM_BUF + (kt % NSTG) * BUF_STRIDE;
    const int kbase = kt * GBK;
#pragma unroll
    for (int j = 0; j < 4; j++) {
        const int g = tid + 256 * j;
        const int r = g >> 2, k16 = g & 3;
        const uint32_t doff = SWZ64((uint32_t)(r * 64 + k16 * 16));
        const uint64_t aoff = ((uint64_t)(row0 + r) * GKD + kbase + k16 * 8) * 2;
        const uint64_t boff = ((uint64_t)(col0 + r) * GKD + kbase + k16 * 8) * 2;
        cp16(bufu + OFF_AH + doff, ahg + aoff);
        cp16(bufu + OFF_AL + doff, alg + aoff);
        cp16(bufu + OFF_BH + doff, whg + boff);
        cp16(bufu + OFF_BL + doff, wlg + boff);
    }
    cp_commit();
}

// ---------------------------------------------------------------------------
// GEMM core: C[256,256 tile] = (Ah+Al) @ (Wh+Wl)^T (3-term split) + bias.
// 3-stage ring; MMA batches enqueue back-to-back; slot refill waits only on
// the batch that last read it (overlapped with the batch just enqueued).
// ---------------------------------------------------------------------------
__device__ __forceinline__ void gemm_core(const __nv_bfloat16* __restrict__ Ah,
                                          const __nv_bfloat16* __restrict__ Al,
                                          const __nv_bfloat16* __restrict__ Wh,
                                          const __nv_bfloat16* __restrict__ Wl,
                                          const float* __restrict__ bias,
                                          float* __restrict__ C)
{
    const uint32_t sb = s2u(dynsmem);
    const int tid  = threadIdx.x;
    const int row0 = blockIdx.y * GBM;
    const int col0 = blockIdx.x * GBN;

    if (tid < 32) {
        tmem_alloc(sb + SM_TMEM, 512);
        tmem_relinquish();
    }
    if (tid == 0) {
#pragma unroll
        for (int s = 0; s < NSTG; s++) mbar_init(sb + SM_MBAR + s * 8, 1);
    }
    __syncthreads();

    uint32_t tmem;
    asm volatile("ld.shared.b32 %0, [%1];" : "=r"(tmem) : "r"(sb + SM_TMEM));

    const uint64_t ahg = to_global(Ah);
    const uint64_t alg = to_global(Al);
    const uint64_t whg = to_global(Wh);
    const uint64_t wlg = to_global(Wl);

    // Prologue: stages 0 and 1 in flight.
    issue_cp(sb, ahg, alg, whg, wlg, row0, col0, 0, tid);
    issue_cp(sb, ahg, alg, whg, wlg, row0, col0, 1, tid);

#pragma unroll 1
    for (int kt = 0; kt < GNCH; kt++) {
        // cp(kt) resident (exactly one younger group allowed in flight;
        // the per-iteration empty commit_group keeps the count exact at tail).
        cp_wait1();
        fence_async_smem();
        __syncthreads();

        // 12 MMAs: 2 M-halves x (hh, hl, lh) x 2 k-steps.
        if (tid < 32) {
            if (elect1()) {
                const uint32_t bufu = sb + SM_BUF + (kt % NSTG) * BUF_STRIDE;
                const uint64_t dBh = mkdesc64(bufu + OFF_BH);
                const uint64_t dBl = mkdesc64(bufu + OFF_BL);
#pragma unroll
                for (int h = 0; h < 2; h++) {
                    const uint64_t dAh = mkdesc64(bufu + OFF_AH + h * 8192);
                    const uint64_t dAl = mkdesc64(bufu + OFF_AL + h * 8192);
                    const uint32_t D = tmem + h * 256;
#pragma unroll
                    for (int ks = 0; ks < 2; ks++)
                        mma_bf16(D, dAh + 2 * ks, dBh + 2 * ks, IDESC_BF16,
                                 (kt == 0 && ks == 0) ? 0u : 1u);
#pragma unroll
                    for (int ks = 0; ks < 2; ks++)
                        mma_bf16(D, dAh + 2 * ks, dBl + 2 * ks, IDESC_BF16, 1u);
#pragma unroll
                    for (int ks = 0; ks < 2; ks++)
                        mma_bf16(D, dAl + 2 * ks, dBh + 2 * ks, IDESC_BF16, 1u);
                }
                tc_commit(sb + SM_MBAR + (kt % NSTG) * 8);
            }
        }

        // Refill slot (kt+2)%NSTG once MMA(kt-1) (its last reader) is done.
        // That wait overlaps the MMA batch just enqueued.
        if (kt + 2 < GNCH) {
            if (kt >= 1) {
                const int s = kt - 1;
                mbar_wait(sb + SM_MBAR + (s % NSTG) * 8, (uint32_t)((s / NSTG) & 1));
            }
            issue_cp(sb, ahg, alg, whg, wlg, row0, col0, kt + 2, tid);
        } else {
            cp_commit();   // empty group: keeps wait_group counting exact
        }
    }

    // Drain the final MMA batch (in-order completion covers all prior).
    {
        const int s = GNCH - 1;
        mbar_wait(sb + SM_MBAR + (s % NSTG) * 8, (uint32_t)((s / NSTG) & 1));
    }
    tc_fence_after();

    // Epilogue: 8 warps. Warp w: M-half = w>>2, lanes = (w&3)*32 + lid.
    {
        const int w    = tid >> 5;
        const int lid  = tid & 31;
        const int half = w >> 2;
        const int m    = row0 + half * 128 + (w & 3) * 32 + lid;
        float* Crow = C + (size_t)m * HIDN + col0;
        const uint32_t Dbase = tmem + half * 256;
#pragma unroll
        for (int n0 = 0; n0 < GBN; n0 += 32) {
            uint32_t r[32];
            TC_LD_X32(r, Dbase + n0);
            tc_wait_ld();
#pragma unroll
            for (int j = 0; j < 32; j += 4) {
                float4 o;
                o.x = __uint_as_float(r[j + 0]) + bias[col0 + n0 + j + 0];
                o.y = __uint_as_float(r[j + 1]) + bias[col0 + n0 + j + 1];
                o.z = __uint_as_float(r[j + 2]) + bias[col0 + n0 + j + 2];
                o.w = __uint_as_float(r[j + 3]) + bias[col0 + n0 + j + 3];
                *(float4*)(Crow + n0 + j) = o;
            }
        }
    }
    __syncthreads();
    if (tid < 32) tmem_dealloc(tmem, 512);
}
#endif  // HAS_TC

// Merged QKV GEMM (z selects pre-split input/weight/bias/output).
__global__ __launch_bounds__(256, 1)
void gemm_qkv(const __nv_bfloat16* __restrict__ ah, const __nv_bfloat16* __restrict__ al,
              const __nv_bfloat16* __restrict__ wh, const __nv_bfloat16* __restrict__ wl,
              const float* __restrict__ bq, const float* __restrict__ bk,
              const float* __restrict__ bv,
              float* __restrict__ oq, float* __restrict__ ok, float* __restrict__ ov)
{
#if HAS_TC
    const int z = blockIdx.z;
    const float* bias = (z == 0) ? bq : (z == 1) ? bk : bv;
    float* C = (z == 0) ? oq : (z == 1) ? ok : ov;
    const size_t ao = (size_t)z * MK;
    const size_t wo = (size_t)z * HIDN * HIDN;
    gemm_core(ah + ao, al + ao, wh + wo, wl + wo, bias, C);
#endif
}

// Single GEMM (output projection; also the runtime capability probe).
__global__ __launch_bounds__(256, 1)
void gemm_single(const __nv_bfloat16* __restrict__ ah, const __nv_bfloat16* __restrict__ al,
                 const __nv_bfloat16* __restrict__ wh, const __nv_bfloat16* __restrict__ wl,
                 const float* __restrict__ bias, float* __restrict__ C)
{
#if HAS_TC
    gemm_core(ah, al, wh, wl, bias, C);
#endif
}

// ===========================================================================
// Activation split: fp32 q/k/v -> bf16 hi/lo (z selects source matrix).
// ===========================================================================
__global__ __launch_bounds__(256)
void split_acts(const float* __restrict__ q, const float* __restrict__ k,
                const float* __restrict__ v,
                __nv_bfloat16* __restrict__ ah, __nv_bfloat16* __restrict__ al)
{
    const int z = blockIdx.z;
    const float* src = (z == 0) ? q : (z == 1) ? k : v;
    __nv_bfloat16* dh = ah + (size_t)z * MK;
    __nv_bfloat16* dl = al + (size_t)z * MK;
    const size_t i = ((size_t)blockIdx.x * 256 + threadIdx.x) * 4;
    const float4 x = *(const float4*)(src + i);
    __nv_bfloat162 h0 = __floats2bfloat162_rn(x.x, x.y);
    __nv_bfloat162 h1 = __floats2bfloat162_rn(x.z, x.w);
    const float2 f0 = __bfloat1622float2(h0);
    const float2 f1 = __bfloat1622float2(h1);
    __nv_bfloat162 l0 = __floats2bfloat162_rn(x.x - f0.x, x.y - f0.y);
    __nv_bfloat162 l1 = __floats2bfloat162_rn(x.z - f1.x, x.w - f1.y);
    *(uint2*)(dh + i) = make_uint2(*(uint32_t*)&h0, *(uint32_t*)&h1);
    *(uint2*)(dl + i) = make_uint2(*(uint32_t*)&l0, *(uint32_t*)&l1);
}

// ===========================================================================
// Weight prep: WTh[n][k] = bf16(W[k][n]), WTl = bf16(residual). 4 matrices.
// ===========================================================================
__global__ __launch_bounds__(256)
void prep_weights(const float* __restrict__ s0, const float* __restrict__ s1,
                  const float* __restrict__ s2, const float* __restrict__ s3,
                  __nv_bfloat16* __restrict__ dh, __nv_bfloat16* __restrict__ dl)
{
    __shared__ float t[32][33];
    const float* src = (blockIdx.z == 0) ? s0 : (blockIdx.z == 1) ? s1
                     : (blockIdx.z == 2) ? s2 : s3;
    const size_t zo = (size_t)blockIdx.z * HIDN * HIDN;
    const int x0 = blockIdx.x * 32, y0 = blockIdx.y * 32;   // x: n, y: k
    const int tx = threadIdx.x & 31, ty0 = threadIdx.x >> 5;
#pragma unroll
    for (int i = 0; i < 4; i++) {
        const int ty = ty0 + i * 8;
        t[ty][tx] = src[(size_t)(y0 + ty) * HIDN + x0 + tx];
    }
    __syncthreads();
#pragma unroll
    for (int i = 0; i < 4; i++) {
        const int ty = ty0 + i * 8;
        const float val = t[tx][ty];
        const __nv_bfloat16 h = __float2bfloat16_rn(val);
        const __nv_bfloat16 l = __float2bfloat16_rn(val - __bfloat162float(h));
        const size_t di = zo + (size_t)(x0 + ty) * HIDN + (y0 + tx);
        dh[di] = h;
        dl[di] = l;
    }
}

// ===========================================================================
// Fallback SGEMM (fp32, proven path) — compiles on every arch.
// ===========================================================================
#define BM 128
#define BN 128
#define BK 16

__global__ __launch_bounds__(256, 2)
void sgemm_bias(const float* __restrict__ A, const float* __restrict__ W,
                const float* __restrict__ bias, float* __restrict__ C,
                int M, int N, int K)
{
    __shared__ float As[2][BK][BM];
    __shared__ float Bs[2][BK][BN];

    const int tid = threadIdx.x;
    const int tx  = tid & 15;
    const int ty  = tid >> 4;
    const int row0 = blockIdx.y * BM;
    const int col0 = blockIdx.x * BN;

    const int a_r = tid >> 2;
    const int a_k = (tid & 3) << 2;
    const int b_r = tid >> 5;
    const int b_c = (tid & 31) << 2;

    const float* Ab = A + (size_t)row0 * K;

    float acc[8][8];
#pragma unroll
    for (int i = 0; i < 8; i++)
#pragma unroll
        for (int j = 0; j < 8; j++) acc[i][j] = 0.f;

    {
        float4 a0 = *(const float4*)(Ab + (size_t)a_r * K + a_k);
        float4 a1 = *(const float4*)(Ab + (size_t)(a_r + 64) * K + a_k);
        float4 w0 = *(const float4*)(W + (size_t)b_r * N + col0 + b_c);
        float4 w1 = *(const float4*)(W + (size_t)(b_r + 8) * N + col0 + b_c);
        As[0][a_k + 0][a_r] = a0.x; As[0][a_k + 1][a_r] = a0.y;
        As[0][a_k + 2][a_r] = a0.z; As[0][a_k + 3][a_r] = a0.w;
        As[0][a_k + 0][a_r + 64] = a1.x; As[0][a_k + 1][a_r + 64] = a1.y;
        As[0][a_k + 2][a_r + 64] = a1.z; As[0][a_k + 3][a_r + 64] = a1.w;
        *(float4*)&Bs[0][b_r][b_c]     = w0;
        *(float4*)&Bs[0][b_r + 8][b_c] = w1;
    }
    __syncthreads();

    const int NT = K / BK;
    for (int kt = 0; kt < NT; kt++) {
        const int cur = kt & 1;

        float4 a0, a1, w0, w1;
        const bool more = (kt + 1 < NT);
        if (more) {
            const float* Ap = Ab + (size_t)(kt + 1) * BK;
            a0 = *(const float4*)(Ap + (size_t)a_r * K + a_k);
            a1 = *(const float4*)(Ap + (size_t)(a_r + 64) * K + a_k);
            const float* Wp = W + (size_t)(kt + 1) * BK * N + col0;
            w0 = *(const float4*)(Wp + (size_t)b_r * N + b_c);
            w1 = *(const float4*)(Wp + (size_t)(b_r + 8) * N + b_c);
        }

#pragma unroll
        for (int kk = 0; kk < BK; kk++) {
            float ar[8], br[8];
            *(float4*)(ar)     = *(const float4*)&As[cur][kk][ty * 8];
            *(float4*)(ar + 4) = *(const float4*)&As[cur][kk][ty * 8 + 4];
            *(float4*)(br)     = *(const float4*)&Bs[cur][kk][tx * 8];
            *(float4*)(br + 4) = *(const float4*)&Bs[cur][kk][tx * 8 + 4];
#pragma unroll
            for (int i = 0; i < 8; i++)
#pragma unroll
                for (int j = 0; j < 8; j++)
                    acc[i][j] += ar[i] * br[j];
        }

        if (more) {
            const int nxt = cur ^ 1;
            As[nxt][a_k + 0][a_r] = a0.x; As[nxt][a_k + 1][a_r] = a0.y;
            As[nxt][a_k + 2][a_r] = a0.z; As[nxt][a_k + 3][a_r] = a0.w;
            As[nxt][a_k + 0][a_r + 64] = a1.x; As[nxt][a_k + 1][a_r + 64] = a1.y;
            As[nxt][a_k + 2][a_r + 64] = a1.z; As[nxt][a_k + 3][a_r + 64] = a1.w;
            *(float4*)&Bs[nxt][b_r][b_c]     = w0;
            *(float4*)&Bs[nxt][b_r + 8][b_c] = w1;
        }
        __syncthreads();
    }

#pragma unroll
    for (int i = 0; i < 8; i++) {
        const size_t r = (size_t)(row0 + ty * 8 + i);
#pragma unroll
        for (int j4 = 0; j4 < 8; j4 += 4) {
            const int c = col0 + tx * 8 + j4;
            float4 o;
            o.x = acc[i][j4 + 0] + bias[c + 0];
            o.y = acc[i][j4 + 1] + bias[c + 1];
            o.z = acc[i][j4 + 2] + bias[c + 2];
            o.w = acc[i][j4 + 3] + bias[c + 3];
            *(float4*)&C[r * N + c] = o;
        }
    }
}

// ===========================================================================
// Per-token attention over the HEADS axis (R12 version, unchanged).
// ===========================================================================
#define PD 68

__global__ __launch_bounds__(256, 5)
void attn_kernel(const float* __restrict__ q, const float* __restrict__ k,
                 const float* __restrict__ v, const float* __restrict__ sw,
                 float* __restrict__ xf,
                 __nv_bfloat16* __restrict__ xh, __nv_bfloat16* __restrict__ xl,
                 float* __restrict__ attn_out, int write_attn, int out_bf16)
{
    __shared__ float sq[NH][PD], sk[NH][PD], sv[NH][PD];
    __shared__ float s_qk[NH][NH];
    __shared__ float s_qn2[NH], s_kn2[NH];
    __shared__ float s_at[NH][NH + 1];

    const int t   = blockIdx.x;
    const int b   = t >> 12;
    const int s   = t & 4095;
    const int tid = threadIdx.x;
    const size_t base = (size_t)t * HIDN;

    {
        const int row = tid >> 4;
        const int col = (tid & 15) << 2;
        *(float4*)&sq[row][col] = *(const float4*)(q + base + row * HD + col);
        *(float4*)&sk[row][col] = *(const float4*)(k + base + row * HD + col);
        *(float4*)&sv[row][col] = *(const float4*)(v + base + row * HD + col);
    }
    __syncthreads();

    if (tid < 32) {
        const int i = tid & 15;
        const float* p = (tid < 16) ? sq[i] : sk[i];
        float ss = 0.f;
#pragma unroll
        for (int d4 = 0; d4 < 16; d4++) {
            const float4 a = *(const float4*)(p + d4 * 4);
            ss += a.x * a.x + a.y * a.y + a.z * a.z + a.w * a.w;
        }
        if (tid < 16) s_qn2[i] = ss; else s_kn2[i] = ss;
    }
    {
        const int i = tid >> 4, j = tid & 15;
        float dot = 0.f;
#pragma unroll
        for (int d4 = 0; d4 < 16; d4++) {
            const float4 a = *(const float4*)&sq[i][d4 * 4];
            const float4 c = *(const float4*)&sk[j][d4 * 4];
            dot += a.x * c.x + a.y * c.y + a.z * c.z + a.w * c.w;
        }
        s_qk[i][j] = dot;
    }
    __syncthreads();

    if (tid < NH) {
        float w0, w1, w2;
        {
            const float x0 = sw[0], x1 = sw[1], x2 = sw[2];
            const float m  = fmaxf(x0, fmaxf(x1, x2));
            const float e0 = expf(x0 - m), e1 = expf(x1 - m), e2 = expf(x2 - m);
            const float inv = 1.f / (e0 + e1 + e2);
            w0 = e0 * inv; w1 = e1 * inv; w2 = e2 * inv;
        }
        const int i = tid;
        const float qn2 = s_qn2[i];
        const float qn  = sqrtf(qn2);
        float sc[NH];
        float mx = -1e30f;
#pragma unroll
        for (int j = 0; j < NH; j++) {
            const float qkv  = s_qk[i][j];
            const float kn2  = s_kn2[j];
            const float dotv = qkv * 0.125f;
            const float cosv = qkv / fmaxf(qn * sqrtf(kn2), 1e-8f);
            const float d2   = fmaxf(qn2 + kn2 - 2.f * qkv, 0.f);
            const float dstv = -sqrtf(d2);
            const float scv  = w0 * dotv + w1 * cosv + w2 * dstv;
            sc[j] = scv;
            mx = fmaxf(mx, scv);
        }
        float ssum = 0.f;
#pragma unroll
        for (int j = 0; j < NH; j++) { const float e = expf(sc[j] - mx); sc[j] = e; ssum += e; }
        const float inv = 1.f / ssum;
#pragma unroll
        for (int j = 0; j < NH; j++) {
            const float a = sc[j] * inv;
            s_at[i][j] = a;
            if (write_attn)
                attn_out[(size_t)t * (NH * NH) + i * NH + j] = a;
        }
    }
    __syncthreads();

    {
        const int i  = tid >> 4;
        const int db = (tid & 15) << 2;
        float4 o = make_float4(0.f, 0.f, 0.f, 0.f);
#pragma unroll
        for (int j = 0; j < NH; j++) {
            const float a = s_at[i][j];
            const float4 vv = *(const float4*)&sv[j][db];
            o.x += a * vv.x; o.y += a * vv.y; o.z += a * vv.z; o.w += a * vv.w;
        }
        // transpose(1,2).reshape fold: row = h*256 + s/16, col = (s%16)*64 + d
        const size_t dst = (size_t)b * ((size_t)SEQ * HIDN)
                         + (size_t)((i << 8) + (s >> 4)) * HIDN
                         + (size_t)((s & 15) << 6) + db;
        if (out_bf16) {
            __nv_bfloat162 h0 = __floats2bfloat162_rn(o.x, o.y);
            __nv_bfloat162 h1 = __floats2bfloat162_rn(o.z, o.w);
            const float2 f0 = __bfloat1622float2(h0);
            const float2 f1 = __bfloat1622float2(h1);
            __nv_bfloat162 l0 = __floats2bfloat162_rn(o.x - f0.x, o.y - f0.y);
            __nv_bfloat162 l1 = __floats2bfloat162_rn(o.z - f1.x, o.w - f1.y);
            *(uint2*)(xh + dst) = make_uint2(*(uint32_t*)&h0, *(uint32_t*)&h1);
            *(uint2*)(xl + dst) = make_uint2(*(uint32_t*)&l0, *(uint32_t*)&l1);
        } else {
            *(float4*)&xf[dst] = o;
        }
    }
}

// ===========================================================================
extern "C" void kernel_launch(void* const* d_in, const int* in_sizes, int n_in,
                              void* d_out, int out_size)
{
    const float* query = (const float*)d_in[0];
    const float* key_  = (const float*)d_in[1];
    const float* value = (const float*)d_in[2];
    const float* Wq    = (const float*)d_in[3];
    const float* bq    = (const float*)d_in[4];
    const float* Wk    = (const float*)d_in[5];
    const float* bk    = (const float*)d_in[6];
    const float* Wv    = (const float*)d_in[7];
    const float* bv    = (const float*)d_in[8];
    const float* Wo    = (const float*)d_in[9];
    const float* bo    = (const float*)d_in[10];
    const float* sw    = (const float*)d_in[11];
    float* out = (float*)d_out;

    float *gq, *gk, *gv, *gx;
    __nv_bfloat16 *gah, *gal, *gxh, *gxl, *gwh, *gwl;
    cudaGetSymbolAddress((void**)&gq,  g_q);
    cudaGetSymbolAddress((void**)&gk,  g_k);
    cudaGetSymbolAddress((void**)&gv,  g_v);
    cudaGetSymbolAddress((void**)&gx,  g_x);
    cudaGetSymbolAddress((void**)&gah, g_ah);
    cudaGetSymbolAddress((void**)&gal, g_al);
    cudaGetSymbolAddress((void**)&gxh, g_xh);
    cudaGetSymbolAddress((void**)&gxl, g_xl);
    cudaGetSymbolAddress((void**)&gwh, g_wbh);
    cudaGetSymbolAddress((void**)&gwl, g_wbl);

    const long long main_elems = (long long)MTOT * HIDN;
    const long long attn_elems = (long long)MTOT * NH * NH;
    const int write_attn = ((long long)out_size >= main_elems + attn_elems) ? 1 : 0;
    float* attn_ptr = out + main_elems;

    // Capability probe: stubbed (non-'a' pass) kernel uses only a few regs.
    cudaFuncAttributes fa;
    fa.numRegs = 0;
    cudaError_t perr = cudaFuncGetAttributes(&fa, gemm_single);
    const bool use_tc = (perr == cudaSuccess) && (fa.numRegs >= 24);

    if (use_tc) {
        cudaFuncSetAttribute(gemm_qkv, cudaFuncAttributeMaxDynamicSharedMemorySize,
                             GEMM_SMEM_BYTES);
        cudaFuncSetAttribute(gemm_single, cudaFuncAttributeMaxDynamicSharedMemorySize,
                             GEMM_SMEM_BYTES);

        // Prep: transpose+split weights; split activations.
        prep_weights<<<dim3(32, 32, 4), 256>>>(Wq, Wk, Wv, Wo, gwh, gwl);
        split_acts<<<dim3(MTOT * HIDN / 1024, 1, 3), 256>>>(query, key_, value, gah, gal);

        const size_t WSZ = (size_t)HIDN * HIDN;
        dim3 gq3(HIDN / GBN, MTOT / GBM, 3);   // (4, 64, 3)
        dim3 gg1(HIDN / GBN, MTOT / GBM);      // (4, 64)

        gemm_qkv<<<gq3, 256, GEMM_SMEM_BYTES>>>(gah, gal, gwh, gwl,
                                                bq, bk, bv, gq, gk, gv);

        attn_kernel<<<MTOT, 256>>>(gq, gk, gv, sw, gx, gxh, gxl,
                                   attn_ptr, write_attn, 1);

        gemm_single<<<gg1, 256, GEMM_SMEM_BYTES>>>(gxh, gxl, gwh + 3 * WSZ,
                                                   gwl + 3 * WSZ, bo, out);
    } else {
        // Fallback: proven fp32 path.
        dim3 gg(HIDN / BN, MTOT / BM);
        sgemm_bias<<<gg, 256>>>(query, Wq, bq, gq, MTOT, HIDN, HIDN);
        sgemm_bias<<<gg, 256>>>(key_,  Wk, bk, gk, MTOT, HIDN, HIDN);
        sgemm_bias<<<gg, 256>>>(value, Wv, bv, gv, MTOT, HIDN, HIDN);

        attn_kernel<<<MTOT, 256>>>(gq, gk, gv, sw, gx, nullptr, nullptr,
                                   attn_ptr, write_attn, 0);

        sgemm_bias<<<gg, 256>>>(gx, Wo, bo, out, MTOT, HIDN, HIDN);
    }
}